// round 2
// baseline (speedup 1.0000x reference)
#include <cuda_runtime.h>
#include <cuda_bf16.h>
#include <cstdint>

// Problem constants (fixed by dataset)
constexpr int NV = 32768;          // B*N nodes
constexpr int Hd = 128;            // hidden
constexpr int NE = 524288;         // edges
constexpr int NR = 8;              // relations
constexpr int NL = 2;              // layers

// Scratch (static device globals; no allocation at runtime)
__device__ float g_x  [(size_t)NV * Hd];
__device__ float g_x2 [(size_t)NV * Hd];
__device__ float g_agg[(size_t)NV * Hd];
__device__ float g_deg[NV];
__device__ float g_y  [(size_t)(NR + 1) * NV * Hd];   // slab 0 = self term, slabs 1..8 = relations

// ---------------------------------------------------------------------------
// Tiled fp32 GEMM: C[v,g] = sum_h A[v,h] * W[g,h]    (both operands K-major)
// BM=BN=128, BK=32, 256 threads, 8x8 register tile per thread.
// MODE 0: A = concept_emb[cid] + kind_emb[kid] (gathered), W = proj_W, +bias
// MODE 1: A = node states, blockIdx.y selects W: 0 -> self_W, 1..8 -> rel_W[r]
// ---------------------------------------------------------------------------
template <int MODE>
__launch_bounds__(256)
__global__ void gemm_kernel(const float* __restrict__ Asrc,
                            const int*   __restrict__ cid,
                            const int*   __restrict__ kid,
                            const float* __restrict__ cemb,
                            const float* __restrict__ kemb,
                            const float* __restrict__ selfW,
                            const float* __restrict__ relW,   // MODE0: proj_W
                            const float* __restrict__ bias,   // MODE0 only
                            float* __restrict__ Cout)
{
    __shared__ float As[32][132];
    __shared__ float Ws[32][132];
    __shared__ int   s_cid[128];
    __shared__ int   s_kid[128];

    const int tid = threadIdx.x;
    const int tx = tid & 15;
    const int ty = tid >> 4;
    const int vbase = blockIdx.x * 128;

    const float* W;
    float* C;
    if (MODE == 0) {
        W = relW;
        C = Cout + (size_t)vbase * Hd;
    } else {
        const int j = blockIdx.y;
        W = (j == 0) ? selfW : (relW + (size_t)(j - 1) * Hd * Hd);
        C = Cout + ((size_t)j * NV + (size_t)vbase) * Hd;
    }

    if (MODE == 0) {
        if (tid < 128) {
            s_cid[tid] = cid[vbase + tid];
            s_kid[tid] = kid[vbase + tid];
        }
        __syncthreads();
    }

    float acc[8][8];
#pragma unroll
    for (int i = 0; i < 8; i++)
#pragma unroll
        for (int j = 0; j < 8; j++) acc[i][j] = 0.0f;

#pragma unroll
    for (int kc = 0; kc < Hd; kc += 32) {
        // Load A tile (transpose to k-major) and W tile.
#pragma unroll
        for (int rep = 0; rep < 4; rep++) {
            const int i   = tid + rep * 256;   // 0..1023
            const int row = i >> 3;            // 0..127
            const int c4  = i & 7;             // 0..7
            float4 a;
            if (MODE == 0) {
                const float4* cr = (const float4*)(cemb + (size_t)s_cid[row] * Hd + kc);
                const float4* kr = (const float4*)(kemb + (size_t)s_kid[row] * Hd + kc);
                const float4 av = cr[c4];
                const float4 kv = kr[c4];
                a = make_float4(av.x + kv.x, av.y + kv.y, av.z + kv.z, av.w + kv.w);
            } else {
                a = *(const float4*)(Asrc + (size_t)(vbase + row) * Hd + kc + c4 * 4);
            }
            As[c4 * 4 + 0][row] = a.x;
            As[c4 * 4 + 1][row] = a.y;
            As[c4 * 4 + 2][row] = a.z;
            As[c4 * 4 + 3][row] = a.w;

            const float4 w = *(const float4*)(W + (size_t)row * Hd + kc + c4 * 4);
            Ws[c4 * 4 + 0][row] = w.x;
            Ws[c4 * 4 + 1][row] = w.y;
            Ws[c4 * 4 + 2][row] = w.z;
            Ws[c4 * 4 + 3][row] = w.w;
        }
        __syncthreads();

#pragma unroll
        for (int k = 0; k < 32; k++) {
            const float4 a0 = *(const float4*)&As[k][ty * 8];
            const float4 a1 = *(const float4*)&As[k][ty * 8 + 4];
            const float4 w0 = *(const float4*)&Ws[k][tx * 8];
            const float4 w1 = *(const float4*)&Ws[k][tx * 8 + 4];
            const float a[8] = {a0.x, a0.y, a0.z, a0.w, a1.x, a1.y, a1.z, a1.w};
            const float w[8] = {w0.x, w0.y, w0.z, w0.w, w1.x, w1.y, w1.z, w1.w};
#pragma unroll
            for (int i = 0; i < 8; i++)
#pragma unroll
                for (int j = 0; j < 8; j++) acc[i][j] += a[i] * w[j];
        }
        __syncthreads();
    }

    // Epilogue
    float b0[8];
    if (MODE == 0) {
#pragma unroll
        for (int j = 0; j < 8; j++) b0[j] = bias[tx * 8 + j];
    }
#pragma unroll
    for (int i = 0; i < 8; i++) {
        const int row = ty * 8 + i;
        float4 v0, v1;
        if (MODE == 0) {
            v0 = make_float4(acc[i][0] + b0[0], acc[i][1] + b0[1],
                             acc[i][2] + b0[2], acc[i][3] + b0[3]);
            v1 = make_float4(acc[i][4] + b0[4], acc[i][5] + b0[5],
                             acc[i][6] + b0[6], acc[i][7] + b0[7]);
        } else {
            v0 = make_float4(acc[i][0], acc[i][1], acc[i][2], acc[i][3]);
            v1 = make_float4(acc[i][4], acc[i][5], acc[i][6], acc[i][7]);
        }
        *(float4*)(C + (size_t)row * Hd + tx * 8)     = v0;
        *(float4*)(C + (size_t)row * Hd + tx * 8 + 4) = v1;
    }
}

// ---------------------------------------------------------------------------
// Edge scatter: one warp per edge. agg[dst] += Y[type+1][src]  (128 floats)
// ---------------------------------------------------------------------------
__launch_bounds__(256)
__global__ void scatter_kernel(const int* __restrict__ src,
                               const int* __restrict__ dst,
                               const int* __restrict__ et,
                               const float* __restrict__ y,
                               float* __restrict__ agg)
{
    const int e    = blockIdx.x * 8 + (threadIdx.x >> 5);
    const int lane = threadIdx.x & 31;
    const int s = src[e];   // 32-lane broadcast loads
    const int d = dst[e];
    const int t = et[e];

    const float4* yr = (const float4*)(y + ((size_t)(t + 1) * NV + (size_t)s) * Hd);
    const float4 v = yr[lane];
    float* a = agg + (size_t)d * Hd + lane * 4;
    asm volatile("red.global.add.v4.f32 [%0], {%1,%2,%3,%4};"
                 :: "l"(a), "f"(v.x), "f"(v.y), "f"(v.z), "f"(v.w)
                 : "memory");
}

__launch_bounds__(256)
__global__ void deg_kernel(const int* __restrict__ dst, float* __restrict__ deg)
{
    const int e = blockIdx.x * 256 + threadIdx.x;
    atomicAdd(&deg[dst[e]], 1.0f);
}

__launch_bounds__(256)
__global__ void zero_kernel(float* __restrict__ p, int n4)
{
    const int i = blockIdx.x * 256 + threadIdx.x;
    if (i < n4) ((float4*)p)[i] = make_float4(0.f, 0.f, 0.f, 0.f);
}

// x_new = relu(selfY + self_b + agg / max(deg,1)); optionally * mask, written to out
__launch_bounds__(256)
__global__ void update_kernel(const float* __restrict__ y0,
                              const float* __restrict__ agg,
                              const float* __restrict__ deg,
                              const float* __restrict__ selfb,  // [H]
                              const int*   __restrict__ mask,
                              float* __restrict__ out,
                              int apply_mask)
{
    const int idx = blockIdx.x * 256 + threadIdx.x;   // float4 index
    const int v  = idx >> 5;                          // 32 float4 per row
    const int h4 = idx & 31;

    const float4 y = ((const float4*)y0)[idx];
    const float4 a = ((const float4*)agg)[idx];
    const float4 b = ((const float4*)selfb)[h4];
    const float id = 1.0f / fmaxf(deg[v], 1.0f);
    float m = 1.0f;
    if (apply_mask) m = (float)mask[v];

    float4 r;
    r.x = fmaxf(y.x + b.x + a.x * id, 0.0f) * m;
    r.y = fmaxf(y.y + b.y + a.y * id, 0.0f) * m;
    r.z = fmaxf(y.z + b.z + a.z * id, 0.0f) * m;
    r.w = fmaxf(y.w + b.w + a.w * id, 0.0f) * m;
    ((float4*)out)[idx] = r;
}

extern "C" void kernel_launch(void* const* d_in, const int* in_sizes, int n_in,
                              void* d_out, int out_size)
{
    const int*   cid   = (const int*)  d_in[0];
    const int*   kid   = (const int*)  d_in[1];
    const int*   mask  = (const int*)  d_in[2];
    const int*   eidx  = (const int*)  d_in[3];
    const int*   et    = (const int*)  d_in[4];
    const float* cemb  = (const float*)d_in[5];
    const float* kemb  = (const float*)d_in[6];
    const float* projW = (const float*)d_in[7];
    const float* projb = (const float*)d_in[8];
    const float* selfW = (const float*)d_in[9];
    const float* selfb = (const float*)d_in[10];
    const float* relW  = (const float*)d_in[11];

    const int* src = eidx;
    const int* dst = eidx + NE;

    float *x, *x2, *agg, *deg, *y;
    cudaGetSymbolAddress((void**)&x,   g_x);
    cudaGetSymbolAddress((void**)&x2,  g_x2);
    cudaGetSymbolAddress((void**)&agg, g_agg);
    cudaGetSymbolAddress((void**)&deg, g_deg);
    cudaGetSymbolAddress((void**)&y,   g_y);

    // Degrees
    zero_kernel<<<(NV / 4 + 255) / 256, 256>>>(deg, NV / 4);
    deg_kernel<<<NE / 256, 256>>>(dst, deg);

    // Input embedding + projection -> x
    gemm_kernel<0><<<dim3(NV / 128, 1), 256>>>(nullptr, cid, kid, cemb, kemb,
                                               nullptr, projW, projb, x);

    float* cur = x;
    float* nxt = x2;
    for (int l = 0; l < NL; l++) {
        zero_kernel<<<(NV * Hd / 4) / 256, 256>>>(agg, NV * Hd / 4);

        // Y[0] = x @ self_W[l]^T ; Y[1+r] = x @ rel_W[l,r]^T
        gemm_kernel<1><<<dim3(NV / 128, NR + 1), 256>>>(
            cur, nullptr, nullptr, nullptr, nullptr,
            selfW + (size_t)l * Hd * Hd,
            relW  + (size_t)l * NR * Hd * Hd,
            nullptr, y);

        scatter_kernel<<<NE / 8, 256>>>(src, dst, et, y, agg);

        float* outp = (l == NL - 1) ? (float*)d_out : nxt;
        update_kernel<<<(NV * Hd / 4) / 256, 256>>>(y, agg, deg, selfb + (size_t)l * Hd,
                                                    mask, outp, (l == NL - 1) ? 1 : 0);
        float* tmp = cur; cur = nxt; nxt = tmp;
    }
}

// round 4
// speedup vs baseline: 2.2383x; 2.2383x over previous
#include <cuda_runtime.h>
#include <cuda_bf16.h>
#include <cstdint>

// ---------------------------------------------------------------------------
// Arch feature gate: tcgen05 exists only on sm_103a (arch-specific) /
// sm_103f (family-specific). Plain sm_103 compiles the fallback only.
// ---------------------------------------------------------------------------
#if defined(__CUDA_ARCH__) && (defined(__CUDA_ARCH_FEAT_SM103_ALL) || \
    (defined(__CUDA_ARCH_FAMILY_SPECIFIC__) && (__CUDA_ARCH_FAMILY_SPECIFIC__ == 1030)))
#define TC_OK 1
#else
#define TC_OK 0
#endif

// Problem constants (fixed by dataset)
constexpr int NV = 32768;          // B*N nodes
constexpr int Hd = 128;            // hidden
constexpr int NE = 524288;         // edges
constexpr int NR = 8;              // relations
constexpr int NL = 2;              // layers

// Scratch (static device globals; no allocation at runtime)
__device__ float g_x  [(size_t)NV * Hd];
__device__ float g_x2 [(size_t)NV * Hd];
__device__ float g_agg[(size_t)NV * Hd];
__device__ float g_deg[NV];
__device__ float g_y  [(size_t)(NR + 1) * NV * Hd];   // slab 0 = self, 1..8 = relations
__device__ int   g_tc_flag;

// ---------------------------------------------------------------------------
// Capability probe: each per-arch cubin bakes in its own TC_OK value; the
// cubin the runtime actually selects reports the truth.
// ---------------------------------------------------------------------------
__global__ void probe_kernel() { g_tc_flag = TC_OK; }

static int detect_tc() {
    int v = 0;
    probe_kernel<<<1, 1>>>();
    cudaMemcpyFromSymbol(&v, g_tc_flag, sizeof(int));   // static-init time, pre-capture
    return v;
}
static const int g_has_tc = detect_tc();

// ---------------------------------------------------------------------------
// PTX helpers (tcgen05 bodies compiled only when TC_OK)
// ---------------------------------------------------------------------------
__device__ __forceinline__ uint32_t smem_u32(const void* p) {
    uint32_t a;
    asm("{ .reg .u64 t; cvta.to.shared.u64 t, %1; cvt.u32.u64 %0, t; }" : "=r"(a) : "l"(p));
    return a;
}
__device__ __forceinline__ uint32_t elect_one() {
    uint32_t p;
    asm volatile("{\n\t.reg .pred p;\n\telect.sync _|p, 0xFFFFFFFF;\n\tselp.b32 %0, 1, 0, p;\n\t}" : "=r"(p));
    return p;
}
__device__ __forceinline__ uint32_t f2tf32(float f) {
    uint32_t u;
    asm("cvt.rna.tf32.f32 %0, %1;" : "=r"(u) : "f"(f));
    return u;
}

#if TC_OK
#define TC_ALLOC(sm, n)   asm volatile("tcgen05.alloc.cta_group::1.sync.aligned.shared::cta.b32 [%0], %1;" :: "r"(sm), "r"(n) : "memory")
#define TC_DEALLOC(t, n)  asm volatile("tcgen05.dealloc.cta_group::1.sync.aligned.b32 %0, %1;" :: "r"(t), "r"(n))
#define TC_RELINQ()       asm volatile("tcgen05.relinquish_alloc_permit.cta_group::1.sync.aligned;")
#define TC_COMMIT(mb)     asm volatile("tcgen05.commit.cta_group::1.mbarrier::arrive::one.shared::cluster.b64 [%0];" :: "r"(mb) : "memory")
#define TC_WAIT_LD()      asm volatile("tcgen05.wait::ld.sync.aligned;" ::: "memory")
#define TC_FENCE_AFTER()  asm volatile("tcgen05.fence::after_thread_sync;" ::: "memory")
#define TC_FENCE_BEFORE() asm volatile("tcgen05.fence::before_thread_sync;" ::: "memory")
#endif

#define MBAR_INIT(mb, c)  asm volatile("mbarrier.init.shared.b64 [%0], %1;" :: "r"(mb), "r"(c) : "memory")
#define MBAR_INVAL(mb)    asm volatile("mbarrier.inval.shared.b64 [%0];" :: "r"(mb) : "memory")

__device__ __forceinline__ void mbar_wait(uint32_t mb, uint32_t parity) {
    asm volatile(
        "{\n\t.reg .pred P1;\n\t"
        "WL_%=:\n\t"
        "mbarrier.try_wait.parity.acquire.cta.shared::cta.b64 P1, [%0], %1, 0x989680;\n\t"
        "@P1 bra.uni WD_%=;\n\t"
        "bra.uni WL_%=;\n\t"
        "WD_%=:\n\t}"
        :: "r"(mb), "r"(parity) : "memory");
}

#if TC_OK
__device__ __forceinline__ void mma_tf32_ss(uint32_t d, uint64_t ad, uint64_t bd,
                                            uint32_t idesc, uint32_t en) {
    asm volatile(
        "{\n\t.reg .pred p;\n\tsetp.ne.u32 p, %5, 0;\n\t"
        "tcgen05.mma.cta_group::1.kind::tf32 [%0], %1, %2, %3, {%4, %4, %4, %4}, p;\n\t}"
        :: "r"(d), "l"(ad), "l"(bd), "r"(idesc), "r"(0u), "r"(en) : "memory");
}

__device__ __forceinline__ void ldtm_x32(uint32_t* r, uint32_t addr) {
    asm volatile(
        "tcgen05.ld.sync.aligned.32x32b.x32.b32 "
        "{%0,%1,%2,%3,%4,%5,%6,%7,%8,%9,%10,%11,%12,%13,%14,%15,"
        "%16,%17,%18,%19,%20,%21,%22,%23,%24,%25,%26,%27,%28,%29,%30,%31}, [%32];"
        : "=r"(r[0]), "=r"(r[1]), "=r"(r[2]), "=r"(r[3]), "=r"(r[4]), "=r"(r[5]), "=r"(r[6]), "=r"(r[7]),
          "=r"(r[8]), "=r"(r[9]), "=r"(r[10]), "=r"(r[11]), "=r"(r[12]), "=r"(r[13]), "=r"(r[14]), "=r"(r[15]),
          "=r"(r[16]), "=r"(r[17]), "=r"(r[18]), "=r"(r[19]), "=r"(r[20]), "=r"(r[21]), "=r"(r[22]), "=r"(r[23]),
          "=r"(r[24]), "=r"(r[25]), "=r"(r[26]), "=r"(r[27]), "=r"(r[28]), "=r"(r[29]), "=r"(r[30]), "=r"(r[31])
        : "r"(addr));
}
#endif

// SW128 K-major blocked-atom layout for a 128x128 fp32 tile.
// atom = 8 rows x 32 floats (1024B); 16 atom-rows, 4 atom-cols;
// atom_offset = atom_row + atom_col*16
__device__ __forceinline__ uint32_t tile_off(int row, int k) {
    uint32_t off = ((uint32_t)((k >> 5) * 16 + (row >> 3)) << 10)
                 + ((uint32_t)(row & 7) << 7) + ((uint32_t)(k & 31) << 2);
    return off ^ ((off >> 3) & 0x70);
}

// smem descriptor: SW128, version=1, LBO=1, SBO=64
__device__ __forceinline__ uint64_t make_desc(uint32_t base) {
    const uint64_t BASE = (uint64_t(2) << 61) | (uint64_t(1) << 46)
                        | (uint64_t(64) << 32) | (uint64_t(1) << 16);
    return BASE | ((uint64_t)(base >> 4) & 0x3FFF);
}

// idesc: dtype=F32(1)<<4, atype=TF32(2)<<7, btype=TF32(2)<<10, N/8<<17, M/16<<24
constexpr uint32_t IDESC_TF32 = (1u << 4) | (2u << 7) | (2u << 10) | (16u << 17) | (8u << 24);

// Dynamic SMEM layout for tc path
constexpr int SMEM_TMEM = 0;
constexpr int SMEM_MBAR = 8;
constexpr int SMEM_A = 1024;
constexpr int SMEM_B = SMEM_A + 65536;
constexpr int SMEM_TOTAL = SMEM_B + 65536 + 128;

// ---------------------------------------------------------------------------
// tcgen05 tf32 GEMM: C[v,g] = sum_h A[v,h] * W[g,h]  (one CTA = 128x128x128)
// MODE 0: A = cemb[cid]+kemb[kid] (gathered), W = proj_W, +bias
// MODE 1: A = node states, blockIdx.y picks W: 0 -> self_W, 1..8 -> rel_W[r]
// Only ever launched when g_has_tc == 1 (body empty otherwise).
// ---------------------------------------------------------------------------
template <int MODE>
__global__ void __launch_bounds__(128, 1)
tgemm_tc(const float* __restrict__ Asrc,
         const int*   __restrict__ cid,
         const int*   __restrict__ kid,
         const float* __restrict__ cemb,
         const float* __restrict__ kemb,
         const float* __restrict__ selfW,
         const float* __restrict__ relW,
         const float* __restrict__ bias,
         float* __restrict__ Cout)
{
#if TC_OK
    extern __shared__ char smem[];
    const uint32_t sb = smem_u32(smem);
    const int tid = threadIdx.x;
    const int wid = tid >> 5;
    const int lid = tid & 31;
    const int vbase = blockIdx.x * 128;

    const float* W;
    float* C;
    if (MODE == 0) {
        W = relW;
        C = Cout + (size_t)vbase * Hd;
    } else {
        const int j = blockIdx.y;
        W = (j == 0) ? selfW : (relW + (size_t)(j - 1) * Hd * Hd);
        C = Cout + ((size_t)j * NV + (size_t)vbase) * Hd;
    }

    if (wid == 0) TC_ALLOC(sb + SMEM_TMEM, 128);
    else          TC_RELINQ();
    __syncthreads();
    uint32_t tmem;
    asm volatile("ld.shared.b32 %0, [%1];" : "=r"(tmem) : "r"(sb + SMEM_TMEM));

    // fill A row + W row (row = tid), converting to tf32, SW128 blocked layout
    {
        const float4* ar;
        const float4* kr = nullptr;
        if (MODE == 0) {
            ar = (const float4*)(cemb + (size_t)cid[vbase + tid] * Hd);
            kr = (const float4*)(kemb + (size_t)kid[vbase + tid] * Hd);
        } else {
            ar = (const float4*)(Asrc + (size_t)(vbase + tid) * Hd);
        }
        const float4* wr = (const float4*)(W + (size_t)tid * Hd);
#pragma unroll
        for (int c4 = 0; c4 < 32; c4++) {
            float4 a = ar[c4];
            if (MODE == 0) {
                const float4 k = kr[c4];
                a.x += k.x; a.y += k.y; a.z += k.z; a.w += k.w;
            }
            uint4 ua = make_uint4(f2tf32(a.x), f2tf32(a.y), f2tf32(a.z), f2tf32(a.w));
            *(uint4*)(smem + SMEM_A + tile_off(tid, c4 * 4)) = ua;

            const float4 w = wr[c4];
            uint4 uw = make_uint4(f2tf32(w.x), f2tf32(w.y), f2tf32(w.z), f2tf32(w.w));
            *(uint4*)(smem + SMEM_B + tile_off(tid, c4 * 4)) = uw;
        }
    }
    asm volatile("fence.proxy.async.shared::cta;" ::: "memory");
    TC_FENCE_BEFORE();
    __syncthreads();

    if (wid == 0) {
        if (elect_one()) MBAR_INIT(sb + SMEM_MBAR, 1);
        __syncwarp();
        TC_FENCE_AFTER();
        const uint64_t ad = make_desc(sb + SMEM_A);
        const uint64_t bd = make_desc(sb + SMEM_B);
        if (elect_one()) {
#pragma unroll
            for (int s = 0; s < 16; s++) {   // 16 K=8 steps
                const uint64_t off = (uint64_t)((s >> 2) * 1024 + (s & 3) * 2);
                mma_tf32_ss(tmem, ad + off, bd + off, IDESC_TF32, s > 0 ? 1u : 0u);
            }
            TC_COMMIT(sb + SMEM_MBAR);
        }
    }
    __syncthreads();
    mbar_wait(sb + SMEM_MBAR, 0);
    TC_FENCE_AFTER();

    // epilogue: warp w owns rows w*32+lid; columns in 4 chunks of 32
    const int row = wid * 32 + lid;
    float* crow = C + (size_t)row * Hd;
#pragma unroll
    for (int ch = 0; ch < 4; ch++) {
        uint32_t d[32];
        ldtm_x32(d, tmem + ch * 32);
        TC_WAIT_LD();
        float f[32];
#pragma unroll
        for (int c = 0; c < 32; c++) {
            f[c] = __uint_as_float(d[c]);
            if (MODE == 0) f[c] += bias[ch * 32 + c];
        }
#pragma unroll
        for (int q = 0; q < 8; q++) {
            *(float4*)(crow + ch * 32 + q * 4) =
                make_float4(f[q * 4], f[q * 4 + 1], f[q * 4 + 2], f[q * 4 + 3]);
        }
    }
    TC_FENCE_BEFORE();
    __syncthreads();
    if (wid == 0) {
        if (elect_one()) MBAR_INVAL(sb + SMEM_MBAR);
        TC_DEALLOC(tmem, 128);
    }
#endif  // TC_OK
}

// ---------------------------------------------------------------------------
// Fallback SIMT fp32 GEMM (round-2, proven): 256 threads, static smem.
// ---------------------------------------------------------------------------
template <int MODE>
__launch_bounds__(256)
__global__ void gemm_fb(const float* __restrict__ Asrc,
                        const int*   __restrict__ cid,
                        const int*   __restrict__ kid,
                        const float* __restrict__ cemb,
                        const float* __restrict__ kemb,
                        const float* __restrict__ selfW,
                        const float* __restrict__ relW,
                        const float* __restrict__ bias,
                        float* __restrict__ Cout)
{
    __shared__ float As[32][132];
    __shared__ float Ws[32][132];
    __shared__ int   s_cid[128];
    __shared__ int   s_kid[128];

    const int tid = threadIdx.x;
    const int tx = tid & 15;
    const int ty = tid >> 4;
    const int vbase = blockIdx.x * 128;

    const float* W;
    float* C;
    if (MODE == 0) {
        W = relW;
        C = Cout + (size_t)vbase * Hd;
    } else {
        const int j = blockIdx.y;
        W = (j == 0) ? selfW : (relW + (size_t)(j - 1) * Hd * Hd);
        C = Cout + ((size_t)j * NV + (size_t)vbase) * Hd;
    }

    if (MODE == 0) {
        if (tid < 128) {
            s_cid[tid] = cid[vbase + tid];
            s_kid[tid] = kid[vbase + tid];
        }
        __syncthreads();
    }

    float acc[8][8];
#pragma unroll
    for (int i = 0; i < 8; i++)
#pragma unroll
        for (int j = 0; j < 8; j++) acc[i][j] = 0.0f;

#pragma unroll
    for (int kc = 0; kc < Hd; kc += 32) {
#pragma unroll
        for (int rep = 0; rep < 4; rep++) {
            const int i   = tid + rep * 256;
            const int row = i >> 3;
            const int c4  = i & 7;
            float4 a;
            if (MODE == 0) {
                const float4* cr = (const float4*)(cemb + (size_t)s_cid[row] * Hd + kc);
                const float4* kr = (const float4*)(kemb + (size_t)s_kid[row] * Hd + kc);
                const float4 av = cr[c4];
                const float4 kv = kr[c4];
                a = make_float4(av.x + kv.x, av.y + kv.y, av.z + kv.z, av.w + kv.w);
            } else {
                a = *(const float4*)(Asrc + (size_t)(vbase + row) * Hd + kc + c4 * 4);
            }
            As[c4 * 4 + 0][row] = a.x;
            As[c4 * 4 + 1][row] = a.y;
            As[c4 * 4 + 2][row] = a.z;
            As[c4 * 4 + 3][row] = a.w;

            const float4 w = *(const float4*)(W + (size_t)row * Hd + kc + c4 * 4);
            Ws[c4 * 4 + 0][row] = w.x;
            Ws[c4 * 4 + 1][row] = w.y;
            Ws[c4 * 4 + 2][row] = w.z;
            Ws[c4 * 4 + 3][row] = w.w;
        }
        __syncthreads();

#pragma unroll
        for (int k = 0; k < 32; k++) {
            const float4 a0 = *(const float4*)&As[k][ty * 8];
            const float4 a1 = *(const float4*)&As[k][ty * 8 + 4];
            const float4 w0 = *(const float4*)&Ws[k][tx * 8];
            const float4 w1 = *(const float4*)&Ws[k][tx * 8 + 4];
            const float a[8] = {a0.x, a0.y, a0.z, a0.w, a1.x, a1.y, a1.z, a1.w};
            const float w[8] = {w0.x, w0.y, w0.z, w0.w, w1.x, w1.y, w1.z, w1.w};
#pragma unroll
            for (int i = 0; i < 8; i++)
#pragma unroll
                for (int j = 0; j < 8; j++) acc[i][j] += a[i] * w[j];
        }
        __syncthreads();
    }

    float b0[8];
    if (MODE == 0) {
#pragma unroll
        for (int j = 0; j < 8; j++) b0[j] = bias[tx * 8 + j];
    }
#pragma unroll
    for (int i = 0; i < 8; i++) {
        const int row = ty * 8 + i;
        float4 v0, v1;
        if (MODE == 0) {
            v0 = make_float4(acc[i][0] + b0[0], acc[i][1] + b0[1],
                             acc[i][2] + b0[2], acc[i][3] + b0[3]);
            v1 = make_float4(acc[i][4] + b0[4], acc[i][5] + b0[5],
                             acc[i][6] + b0[6], acc[i][7] + b0[7]);
        } else {
            v0 = make_float4(acc[i][0], acc[i][1], acc[i][2], acc[i][3]);
            v1 = make_float4(acc[i][4], acc[i][5], acc[i][6], acc[i][7]);
        }
        *(float4*)(C + (size_t)row * Hd + tx * 8)     = v0;
        *(float4*)(C + (size_t)row * Hd + tx * 8 + 4) = v1;
    }
}

// ---------------------------------------------------------------------------
// Edge scatter: one warp per edge. agg[dst] += Y[type+1][src]  (128 floats)
// ---------------------------------------------------------------------------
__launch_bounds__(256)
__global__ void scatter_kernel(const int* __restrict__ src,
                               const int* __restrict__ dst,
                               const int* __restrict__ et,
                               const float* __restrict__ y,
                               float* __restrict__ agg)
{
    const int e    = blockIdx.x * 8 + (threadIdx.x >> 5);
    const int lane = threadIdx.x & 31;
    const int s = src[e];
    const int d = dst[e];
    const int t = et[e];

    const float4* yr = (const float4*)(y + ((size_t)(t + 1) * NV + (size_t)s) * Hd);
    const float4 v = yr[lane];
    float* a = agg + (size_t)d * Hd + lane * 4;
    asm volatile("red.global.add.v4.f32 [%0], {%1,%2,%3,%4};"
                 :: "l"(a), "f"(v.x), "f"(v.y), "f"(v.z), "f"(v.w)
                 : "memory");
}

__launch_bounds__(256)
__global__ void deg_kernel(const int* __restrict__ dst, float* __restrict__ deg)
{
    const int e = blockIdx.x * 256 + threadIdx.x;
    atomicAdd(&deg[dst[e]], 1.0f);
}

__launch_bounds__(256)
__global__ void zero_kernel(float* __restrict__ p, int n4)
{
    const int i = blockIdx.x * 256 + threadIdx.x;
    if (i < n4) ((float4*)p)[i] = make_float4(0.f, 0.f, 0.f, 0.f);
}

// x_new = relu(selfY + self_b + agg / max(deg,1)); optionally * mask
__launch_bounds__(256)
__global__ void update_kernel(const float* __restrict__ y0,
                              const float* __restrict__ agg,
                              const float* __restrict__ deg,
                              const float* __restrict__ selfb,
                              const int*   __restrict__ mask,
                              float* __restrict__ out,
                              int apply_mask)
{
    const int idx = blockIdx.x * 256 + threadIdx.x;
    const int v  = idx >> 5;
    const int h4 = idx & 31;

    const float4 y = ((const float4*)y0)[idx];
    const float4 a = ((const float4*)agg)[idx];
    const float4 b = ((const float4*)selfb)[h4];
    const float id = 1.0f / fmaxf(deg[v], 1.0f);
    float m = 1.0f;
    if (apply_mask) m = (float)mask[v];

    float4 r;
    r.x = fmaxf(y.x + b.x + a.x * id, 0.0f) * m;
    r.y = fmaxf(y.y + b.y + a.y * id, 0.0f) * m;
    r.z = fmaxf(y.z + b.z + a.z * id, 0.0f) * m;
    r.w = fmaxf(y.w + b.w + a.w * id, 0.0f) * m;
    ((float4*)out)[idx] = r;
}

extern "C" void kernel_launch(void* const* d_in, const int* in_sizes, int n_in,
                              void* d_out, int out_size)
{
    const int*   cid   = (const int*)  d_in[0];
    const int*   kid   = (const int*)  d_in[1];
    const int*   mask  = (const int*)  d_in[2];
    const int*   eidx  = (const int*)  d_in[3];
    const int*   et    = (const int*)  d_in[4];
    const float* cemb  = (const float*)d_in[5];
    const float* kemb  = (const float*)d_in[6];
    const float* projW = (const float*)d_in[7];
    const float* projb = (const float*)d_in[8];
    const float* selfW = (const float*)d_in[9];
    const float* selfb = (const float*)d_in[10];
    const float* relW  = (const float*)d_in[11];

    const int* src = eidx;
    const int* dst = eidx + NE;

    float *x, *x2, *agg, *deg, *y;
    cudaGetSymbolAddress((void**)&x,   g_x);
    cudaGetSymbolAddress((void**)&x2,  g_x2);
    cudaGetSymbolAddress((void**)&agg, g_agg);
    cudaGetSymbolAddress((void**)&deg, g_deg);
    cudaGetSymbolAddress((void**)&y,   g_y);

    const int use_tc = g_has_tc;
    if (use_tc) {
        cudaFuncSetAttribute(tgemm_tc<0>, cudaFuncAttributeMaxDynamicSharedMemorySize, SMEM_TOTAL);
        cudaFuncSetAttribute(tgemm_tc<1>, cudaFuncAttributeMaxDynamicSharedMemorySize, SMEM_TOTAL);
    }

    // Degrees
    zero_kernel<<<(NV / 4 + 255) / 256, 256>>>(deg, NV / 4);
    deg_kernel<<<NE / 256, 256>>>(dst, deg);

    // Input embedding + projection -> x
    if (use_tc)
        tgemm_tc<0><<<dim3(NV / 128, 1), 128, SMEM_TOTAL>>>(
            nullptr, cid, kid, cemb, kemb, nullptr, projW, projb, x);
    else
        gemm_fb<0><<<dim3(NV / 128, 1), 256>>>(
            nullptr, cid, kid, cemb, kemb, nullptr, projW, projb, x);

    float* cur = x;
    float* nxt = x2;
    for (int l = 0; l < NL; l++) {
        zero_kernel<<<(NV * Hd / 4) / 256, 256>>>(agg, NV * Hd / 4);

        // Y[0] = x @ self_W[l]^T ; Y[1+r] = x @ rel_W[l,r]^T
        if (use_tc)
            tgemm_tc<1><<<dim3(NV / 128, NR + 1), 128, SMEM_TOTAL>>>(
                cur, nullptr, nullptr, nullptr, nullptr,
                selfW + (size_t)l * Hd * Hd,
                relW  + (size_t)l * NR * Hd * Hd,
                nullptr, y);
        else
            gemm_fb<1><<<dim3(NV / 128, NR + 1), 256>>>(
                cur, nullptr, nullptr, nullptr, nullptr,
                selfW + (size_t)l * Hd * Hd,
                relW  + (size_t)l * NR * Hd * Hd,
                nullptr, y);

        scatter_kernel<<<NE / 8, 256>>>(src, dst, et, y, agg);

        float* outp = (l == NL - 1) ? (float*)d_out : nxt;
        update_kernel<<<(NV * Hd / 4) / 256, 256>>>(y, agg, deg, selfb + (size_t)l * Hd,
                                                    mask, outp, (l == NL - 1) ? 1 : 0);
        float* tmp = cur; cur = nxt; nxt = tmp;
    }
}

// round 5
// speedup vs baseline: 2.8904x; 1.2914x over previous
#include <cuda_runtime.h>
#include <cuda_bf16.h>
#include <cstdint>

// ---------------------------------------------------------------------------
// Arch feature gate: tcgen05 exists only on sm_103a / family 103f.
// ---------------------------------------------------------------------------
#if defined(__CUDA_ARCH__) && (defined(__CUDA_ARCH_FEAT_SM103_ALL) || \
    (defined(__CUDA_ARCH_FAMILY_SPECIFIC__) && (__CUDA_ARCH_FAMILY_SPECIFIC__ == 1030)))
#define TC_OK 1
#else
#define TC_OK 0
#endif

// Problem constants (fixed by dataset)
constexpr int NV = 32768;          // B*N nodes
constexpr int Hd = 128;            // hidden
constexpr int NE = 524288;         // edges
constexpr int NR = 8;              // relations
constexpr int NL = 2;              // layers
constexpr int NSLAB = NR + 1;      // 9: slab 0 = self, 1..8 = relations

// Scratch (static device globals; no allocation at runtime)
__device__ float g_x  [(size_t)NV * Hd];
__device__ float g_x2 [(size_t)NV * Hd];
__device__ float g_agg[(size_t)NV * Hd];
__device__ float g_deg[NV];
__device__ float g_y  [(size_t)NSLAB * NV * Hd];
__device__ int   g_tc_flag;

// ---------------------------------------------------------------------------
// Capability probe (runs at static-init, outside graph capture)
// ---------------------------------------------------------------------------
__global__ void probe_kernel() { g_tc_flag = TC_OK; }

static int detect_tc() {
    int v = 0;
    probe_kernel<<<1, 1>>>();
    cudaMemcpyFromSymbol(&v, g_tc_flag, sizeof(int));
    return v;
}
static const int g_has_tc = detect_tc();

// ---------------------------------------------------------------------------
// PTX helpers
// ---------------------------------------------------------------------------
__device__ __forceinline__ uint32_t smem_u32(const void* p) {
    uint32_t a;
    asm("{ .reg .u64 t; cvta.to.shared.u64 t, %1; cvt.u32.u64 %0, t; }" : "=r"(a) : "l"(p));
    return a;
}
__device__ __forceinline__ uint32_t elect_one() {
    uint32_t p;
    asm volatile("{\n\t.reg .pred p;\n\telect.sync _|p, 0xFFFFFFFF;\n\tselp.b32 %0, 1, 0, p;\n\t}" : "=r"(p));
    return p;
}
__device__ __forceinline__ uint32_t f2tf32(float f) {
    uint32_t u;
    asm("cvt.rna.tf32.f32 %0, %1;" : "=r"(u) : "f"(f));
    return u;
}

#if TC_OK
#define TC_ALLOC(sm, n)   asm volatile("tcgen05.alloc.cta_group::1.sync.aligned.shared::cta.b32 [%0], %1;" :: "r"(sm), "r"(n) : "memory")
#define TC_DEALLOC(t, n)  asm volatile("tcgen05.dealloc.cta_group::1.sync.aligned.b32 %0, %1;" :: "r"(t), "r"(n))
#define TC_RELINQ()       asm volatile("tcgen05.relinquish_alloc_permit.cta_group::1.sync.aligned;")
#define TC_COMMIT(mb)     asm volatile("tcgen05.commit.cta_group::1.mbarrier::arrive::one.shared::cluster.b64 [%0];" :: "r"(mb) : "memory")
#define TC_WAIT_LD()      asm volatile("tcgen05.wait::ld.sync.aligned;" ::: "memory")
#define TC_FENCE_AFTER()  asm volatile("tcgen05.fence::after_thread_sync;" ::: "memory")
#define TC_FENCE_BEFORE() asm volatile("tcgen05.fence::before_thread_sync;" ::: "memory")
#endif

#define MBAR_INIT(mb, c)  asm volatile("mbarrier.init.shared.b64 [%0], %1;" :: "r"(mb), "r"(c) : "memory")
#define MBAR_INVAL(mb)    asm volatile("mbarrier.inval.shared.b64 [%0];" :: "r"(mb) : "memory")

__device__ __forceinline__ void mbar_wait(uint32_t mb, uint32_t parity) {
    asm volatile(
        "{\n\t.reg .pred P1;\n\t"
        "WL_%=:\n\t"
        "mbarrier.try_wait.parity.acquire.cta.shared::cta.b64 P1, [%0], %1, 0x989680;\n\t"
        "@P1 bra.uni WD_%=;\n\t"
        "bra.uni WL_%=;\n\t"
        "WD_%=:\n\t}"
        :: "r"(mb), "r"(parity) : "memory");
}

#if TC_OK
__device__ __forceinline__ void mma_tf32_ss(uint32_t d, uint64_t ad, uint64_t bd,
                                            uint32_t idesc, uint32_t en) {
    asm volatile(
        "{\n\t.reg .pred p;\n\tsetp.ne.u32 p, %5, 0;\n\t"
        "tcgen05.mma.cta_group::1.kind::tf32 [%0], %1, %2, %3, {%4, %4, %4, %4}, p;\n\t}"
        :: "r"(d), "l"(ad), "l"(bd), "r"(idesc), "r"(0u), "r"(en) : "memory");
}

__device__ __forceinline__ void ldtm_x32(uint32_t* r, uint32_t addr) {
    asm volatile(
        "tcgen05.ld.sync.aligned.32x32b.x32.b32 "
        "{%0,%1,%2,%3,%4,%5,%6,%7,%8,%9,%10,%11,%12,%13,%14,%15,"
        "%16,%17,%18,%19,%20,%21,%22,%23,%24,%25,%26,%27,%28,%29,%30,%31}, [%32];"
        : "=r"(r[0]), "=r"(r[1]), "=r"(r[2]), "=r"(r[3]), "=r"(r[4]), "=r"(r[5]), "=r"(r[6]), "=r"(r[7]),
          "=r"(r[8]), "=r"(r[9]), "=r"(r[10]), "=r"(r[11]), "=r"(r[12]), "=r"(r[13]), "=r"(r[14]), "=r"(r[15]),
          "=r"(r[16]), "=r"(r[17]), "=r"(r[18]), "=r"(r[19]), "=r"(r[20]), "=r"(r[21]), "=r"(r[22]), "=r"(r[23]),
          "=r"(r[24]), "=r"(r[25]), "=r"(r[26]), "=r"(r[27]), "=r"(r[28]), "=r"(r[29]), "=r"(r[30]), "=r"(r[31])
        : "r"(addr));
}
#endif

// SW128 K-major blocked-atom layout for a 128x128 fp32 tile.
// atom = 8 rows x 32 floats (1024B); 16 atom-rows, 4 atom-cols.
__device__ __forceinline__ uint32_t tile_off(int row, int k) {
    uint32_t off = ((uint32_t)((k >> 5) * 16 + (row >> 3)) << 10)
                 + ((uint32_t)(row & 7) << 7) + ((uint32_t)(k & 31) << 2);
    return off ^ ((off >> 3) & 0x70);
}

// smem descriptor: SW128, version=1, LBO=1, SBO=64
__device__ __forceinline__ uint64_t make_desc(uint32_t base) {
    const uint64_t BASE = (uint64_t(2) << 61) | (uint64_t(1) << 46)
                        | (uint64_t(64) << 32) | (uint64_t(1) << 16);
    return BASE | ((uint64_t)(base >> 4) & 0x3FFF);
}

// idesc: dtype=F32(1)<<4, atype=TF32(2)<<7, btype=TF32(2)<<10, N/8<<17, M/16<<24
constexpr uint32_t IDESC_TF32 = (1u << 4) | (2u << 7) | (2u << 10) | (16u << 17) | (8u << 24);

// Dynamic SMEM layout
constexpr int SMEM_TMEM = 0;
constexpr int SMEM_MB0  = 8;
constexpr int SMEM_MB1  = 16;
constexpr int SMEM_A    = 1024;
constexpr int SMEM_W0   = SMEM_A  + 65536;
constexpr int SMEM_W1   = SMEM_W0 + 65536;
constexpr int SMEM_TOTAL9 = SMEM_W1 + 65536 + 128;           // ~193 KB (9-slab kernel)
constexpr int SMEM_TOTAL0 = SMEM_W0 + 65536 + 128;           // ~132 KB (proj kernel)

// ---------------------------------------------------------------------------
// MODE0 projection GEMM (round-4 proven): C = (cemb[cid]+kemb[kid]) @ projW^T + b
// ---------------------------------------------------------------------------
__global__ void __launch_bounds__(128, 1)
tgemm_proj(const int* __restrict__ cid, const int* __restrict__ kid,
           const float* __restrict__ cemb, const float* __restrict__ kemb,
           const float* __restrict__ W, const float* __restrict__ bias,
           float* __restrict__ Cout)
{
#if TC_OK
    extern __shared__ char smem[];
    const uint32_t sb = smem_u32(smem);
    const int tid = threadIdx.x;
    const int wid = tid >> 5;
    const int lid = tid & 31;
    const int vbase = blockIdx.x * 128;
    float* C = Cout + (size_t)vbase * Hd;

    if (wid == 0) TC_ALLOC(sb + SMEM_TMEM, 128);
    else          TC_RELINQ();
    __syncthreads();
    uint32_t tmem;
    asm volatile("ld.shared.b32 %0, [%1];" : "=r"(tmem) : "r"(sb + SMEM_TMEM));

    {
        const float4* ar = (const float4*)(cemb + (size_t)cid[vbase + tid] * Hd);
        const float4* kr = (const float4*)(kemb + (size_t)kid[vbase + tid] * Hd);
        const float4* wr = (const float4*)(W + (size_t)tid * Hd);
#pragma unroll
        for (int c4 = 0; c4 < 32; c4++) {
            float4 a = ar[c4];
            const float4 k = kr[c4];
            a.x += k.x; a.y += k.y; a.z += k.z; a.w += k.w;
            *(uint4*)(smem + SMEM_A + tile_off(tid, c4 * 4)) =
                make_uint4(f2tf32(a.x), f2tf32(a.y), f2tf32(a.z), f2tf32(a.w));
            const float4 w = wr[c4];
            *(uint4*)(smem + SMEM_W0 + tile_off(tid, c4 * 4)) =
                make_uint4(f2tf32(w.x), f2tf32(w.y), f2tf32(w.z), f2tf32(w.w));
        }
    }
    asm volatile("fence.proxy.async.shared::cta;" ::: "memory");
    TC_FENCE_BEFORE();
    __syncthreads();

    if (wid == 0) {
        if (elect_one()) MBAR_INIT(sb + SMEM_MB0, 1);
        __syncwarp();
        TC_FENCE_AFTER();
        const uint64_t ad = make_desc(sb + SMEM_A);
        const uint64_t bd = make_desc(sb + SMEM_W0);
        if (elect_one()) {
#pragma unroll
            for (int s = 0; s < 16; s++) {
                const uint64_t off = (uint64_t)((s >> 2) * 1024 + (s & 3) * 2);
                mma_tf32_ss(tmem, ad + off, bd + off, IDESC_TF32, s > 0 ? 1u : 0u);
            }
            TC_COMMIT(sb + SMEM_MB0);
        }
    }
    __syncthreads();
    mbar_wait(sb + SMEM_MB0, 0);
    TC_FENCE_AFTER();

    const int row = wid * 32 + lid;
    float* crow = C + (size_t)row * Hd;
#pragma unroll
    for (int ch = 0; ch < 4; ch++) {
        uint32_t d[32];
        ldtm_x32(d, tmem + ch * 32);
        TC_WAIT_LD();
#pragma unroll
        for (int q = 0; q < 8; q++) {
            *(float4*)(crow + ch * 32 + q * 4) = make_float4(
                __uint_as_float(d[q*4+0]) + bias[ch*32 + q*4+0],
                __uint_as_float(d[q*4+1]) + bias[ch*32 + q*4+1],
                __uint_as_float(d[q*4+2]) + bias[ch*32 + q*4+2],
                __uint_as_float(d[q*4+3]) + bias[ch*32 + q*4+3]);
        }
    }
    TC_FENCE_BEFORE();
    __syncthreads();
    if (wid == 0) {
        if (elect_one()) MBAR_INVAL(sb + SMEM_MB0);
        TC_DEALLOC(tmem, 128);
    }
#endif
}

// ---------------------------------------------------------------------------
// 9-slab GEMM: one CTA = one 128-row x-block; A loaded ONCE; the 9 weight
// matrices (self, rel 0..7) stream through double-buffered smem; D ping-pongs
// between two 128-col TMEM buffers so epilogue(j) overlaps MMA(j+1).
//   Y[j][vbase..vbase+127][:] = A @ W_j^T
// ---------------------------------------------------------------------------
__global__ void __launch_bounds__(128, 1)
tgemm9(const float* __restrict__ Asrc,
       const float* __restrict__ selfW,
       const float* __restrict__ relW,
       float* __restrict__ Yout)
{
#if TC_OK
    extern __shared__ char smem[];
    const uint32_t sb = smem_u32(smem);
    const int tid = threadIdx.x;
    const int wid = tid >> 5;
    const int lid = tid & 31;
    const int vbase = blockIdx.x * 128;

    if (wid == 0) TC_ALLOC(sb + SMEM_TMEM, 256);   // two 128-col D buffers
    else          TC_RELINQ();
    __syncthreads();
    uint32_t tmem;
    asm volatile("ld.shared.b32 %0, [%1];" : "=r"(tmem) : "r"(sb + SMEM_TMEM));

    if (tid == 0) {
        MBAR_INIT(sb + SMEM_MB0, 1);
        MBAR_INIT(sb + SMEM_MB1, 1);
    }

    // Load A row (row = tid) once, convert to tf32, SW128 blocked layout.
    {
        const float4* ar = (const float4*)(Asrc + (size_t)(vbase + tid) * Hd);
#pragma unroll
        for (int c4 = 0; c4 < 32; c4++) {
            const float4 a = ar[c4];
            *(uint4*)(smem + SMEM_A + tile_off(tid, c4 * 4)) =
                make_uint4(f2tf32(a.x), f2tf32(a.y), f2tf32(a.z), f2tf32(a.w));
        }
    }
    // Load W_0 (= selfW) into buffer 0.
    {
        const float4* wr = (const float4*)(selfW + (size_t)tid * Hd);
#pragma unroll
        for (int c4 = 0; c4 < 32; c4++) {
            const float4 w = wr[c4];
            *(uint4*)(smem + SMEM_W0 + tile_off(tid, c4 * 4)) =
                make_uint4(f2tf32(w.x), f2tf32(w.y), f2tf32(w.z), f2tf32(w.w));
        }
    }
    asm volatile("fence.proxy.async.shared::cta;" ::: "memory");
    TC_FENCE_BEFORE();
    __syncthreads();

    const uint64_t ad  = make_desc(sb + SMEM_A);
    const int row = wid * 32 + lid;

    for (int j = 0; j < NSLAB; j++) {
        const int buf = j & 1;
        const uint32_t dtm = tmem + buf * 128;

        // Issue MMA j on wbuf[buf] -> D[buf]
        if (wid == 0) {
            TC_FENCE_AFTER();
            const uint64_t bd = make_desc(sb + (buf ? SMEM_W1 : SMEM_W0));
            if (elect_one()) {
#pragma unroll
                for (int s = 0; s < 16; s++) {
                    const uint64_t off = (uint64_t)((s >> 2) * 1024 + (s & 3) * 2);
                    mma_tf32_ss(dtm, ad + off, bd + off, IDESC_TF32, s > 0 ? 1u : 0u);
                }
                TC_COMMIT(sb + (buf ? SMEM_MB1 : SMEM_MB0));
            }
        }

        // Prefetch W_{j+1} into the other buffer while MMA j runs.
        // (Safe: last MMA reading that buffer, j-1, was waited at iter j-1.)
        if (j + 1 < NSLAB) {
            const float* Wn = relW + (size_t)j * Hd * Hd;   // slab j+1 = rel_W[j]
            const float4* wr = (const float4*)(Wn + (size_t)tid * Hd);
            char* wb = smem + ((j + 1) & 1 ? SMEM_W1 : SMEM_W0);
#pragma unroll
            for (int c4 = 0; c4 < 32; c4++) {
                const float4 w = wr[c4];
                *(uint4*)(wb + tile_off(tid, c4 * 4)) =
                    make_uint4(f2tf32(w.x), f2tf32(w.y), f2tf32(w.z), f2tf32(w.w));
            }
        }

        // Wait for MMA j, then drain D[buf] to Y slab j.
        mbar_wait(sb + (buf ? SMEM_MB1 : SMEM_MB0), (j >> 1) & 1);
        TC_FENCE_AFTER();

        float* crow = Yout + ((size_t)j * NV + (size_t)(vbase + row)) * Hd;
#pragma unroll
        for (int ch = 0; ch < 4; ch++) {
            uint32_t d[32];
            ldtm_x32(d, dtm + ch * 32);
            TC_WAIT_LD();
#pragma unroll
            for (int q = 0; q < 8; q++) {
                *(float4*)(crow + ch * 32 + q * 4) = make_float4(
                    __uint_as_float(d[q*4+0]), __uint_as_float(d[q*4+1]),
                    __uint_as_float(d[q*4+2]), __uint_as_float(d[q*4+3]));
            }
        }
        TC_FENCE_BEFORE();
        asm volatile("fence.proxy.async.shared::cta;" ::: "memory");  // order W prefetch for next MMA
        __syncthreads();
    }

    if (tid == 0) { MBAR_INVAL(sb + SMEM_MB0); MBAR_INVAL(sb + SMEM_MB1); }
    __syncthreads();
    if (wid == 0) TC_DEALLOC(tmem, 256);
#endif
}

// ---------------------------------------------------------------------------
// Fallback SIMT fp32 GEMM (round-2 proven) — used only if tcgen05 unavailable.
// ---------------------------------------------------------------------------
template <int MODE>
__launch_bounds__(256)
__global__ void gemm_fb(const float* __restrict__ Asrc,
                        const int*   __restrict__ cid,
                        const int*   __restrict__ kid,
                        const float* __restrict__ cemb,
                        const float* __restrict__ kemb,
                        const float* __restrict__ selfW,
                        const float* __restrict__ relW,
                        const float* __restrict__ bias,
                        float* __restrict__ Cout)
{
    __shared__ float As[32][132];
    __shared__ float Ws[32][132];
    __shared__ int   s_cid[128];
    __shared__ int   s_kid[128];

    const int tid = threadIdx.x;
    const int tx = tid & 15;
    const int ty = tid >> 4;
    const int vbase = blockIdx.x * 128;

    const float* W;
    float* C;
    if (MODE == 0) {
        W = relW;
        C = Cout + (size_t)vbase * Hd;
    } else {
        const int j = blockIdx.y;
        W = (j == 0) ? selfW : (relW + (size_t)(j - 1) * Hd * Hd);
        C = Cout + ((size_t)j * NV + (size_t)vbase) * Hd;
    }

    if (MODE == 0) {
        if (tid < 128) {
            s_cid[tid] = cid[vbase + tid];
            s_kid[tid] = kid[vbase + tid];
        }
        __syncthreads();
    }

    float acc[8][8];
#pragma unroll
    for (int i = 0; i < 8; i++)
#pragma unroll
        for (int j = 0; j < 8; j++) acc[i][j] = 0.0f;

#pragma unroll
    for (int kc = 0; kc < Hd; kc += 32) {
#pragma unroll
        for (int rep = 0; rep < 4; rep++) {
            const int i   = tid + rep * 256;
            const int r   = i >> 3;
            const int c4  = i & 7;
            float4 a;
            if (MODE == 0) {
                const float4 av = ((const float4*)(cemb + (size_t)s_cid[r] * Hd + kc))[c4];
                const float4 kv = ((const float4*)(kemb + (size_t)s_kid[r] * Hd + kc))[c4];
                a = make_float4(av.x + kv.x, av.y + kv.y, av.z + kv.z, av.w + kv.w);
            } else {
                a = *(const float4*)(Asrc + (size_t)(vbase + r) * Hd + kc + c4 * 4);
            }
            As[c4 * 4 + 0][r] = a.x; As[c4 * 4 + 1][r] = a.y;
            As[c4 * 4 + 2][r] = a.z; As[c4 * 4 + 3][r] = a.w;
            const float4 w = *(const float4*)(W + (size_t)r * Hd + kc + c4 * 4);
            Ws[c4 * 4 + 0][r] = w.x; Ws[c4 * 4 + 1][r] = w.y;
            Ws[c4 * 4 + 2][r] = w.z; Ws[c4 * 4 + 3][r] = w.w;
        }
        __syncthreads();

#pragma unroll
        for (int k = 0; k < 32; k++) {
            const float4 a0 = *(const float4*)&As[k][ty * 8];
            const float4 a1 = *(const float4*)&As[k][ty * 8 + 4];
            const float4 w0 = *(const float4*)&Ws[k][tx * 8];
            const float4 w1 = *(const float4*)&Ws[k][tx * 8 + 4];
            const float a[8] = {a0.x, a0.y, a0.z, a0.w, a1.x, a1.y, a1.z, a1.w};
            const float w[8] = {w0.x, w0.y, w0.z, w0.w, w1.x, w1.y, w1.z, w1.w};
#pragma unroll
            for (int i = 0; i < 8; i++)
#pragma unroll
                for (int j = 0; j < 8; j++) acc[i][j] += a[i] * w[j];
        }
        __syncthreads();
    }

    float b0[8];
    if (MODE == 0) {
#pragma unroll
        for (int j = 0; j < 8; j++) b0[j] = bias[tx * 8 + j];
    }
#pragma unroll
    for (int i = 0; i < 8; i++) {
        const int r = ty * 8 + i;
        float4 v0, v1;
        if (MODE == 0) {
            v0 = make_float4(acc[i][0] + b0[0], acc[i][1] + b0[1],
                             acc[i][2] + b0[2], acc[i][3] + b0[3]);
            v1 = make_float4(acc[i][4] + b0[4], acc[i][5] + b0[5],
                             acc[i][6] + b0[6], acc[i][7] + b0[7]);
        } else {
            v0 = make_float4(acc[i][0], acc[i][1], acc[i][2], acc[i][3]);
            v1 = make_float4(acc[i][4], acc[i][5], acc[i][6], acc[i][7]);
        }
        *(float4*)(C + (size_t)r * Hd + tx * 8)     = v0;
        *(float4*)(C + (size_t)r * Hd + tx * 8 + 4) = v1;
    }
}

// ---------------------------------------------------------------------------
// Edge scatter: one warp per edge. agg[dst] += Y[type+1][src]  (128 floats)
// ---------------------------------------------------------------------------
__launch_bounds__(256)
__global__ void scatter_kernel(const int* __restrict__ src,
                               const int* __restrict__ dst,
                               const int* __restrict__ et,
                               const float* __restrict__ y,
                               float* __restrict__ agg)
{
    const int e    = blockIdx.x * 8 + (threadIdx.x >> 5);
    const int lane = threadIdx.x & 31;
    const int s = src[e];
    const int d = dst[e];
    const int t = et[e];

    const float4* yr = (const float4*)(y + ((size_t)(t + 1) * NV + (size_t)s) * Hd);
    const float4 v = yr[lane];
    float* a = agg + (size_t)d * Hd + lane * 4;
    asm volatile("red.global.add.v4.f32 [%0], {%1,%2,%3,%4};"
                 :: "l"(a), "f"(v.x), "f"(v.y), "f"(v.z), "f"(v.w)
                 : "memory");
}

__launch_bounds__(256)
__global__ void deg_kernel(const int* __restrict__ dst, float* __restrict__ deg)
{
    const int e = blockIdx.x * 256 + threadIdx.x;
    atomicAdd(&deg[dst[e]], 1.0f);
}

__launch_bounds__(256)
__global__ void zero_kernel(float* __restrict__ p, int n4)
{
    const int i = blockIdx.x * 256 + threadIdx.x;
    if (i < n4) ((float4*)p)[i] = make_float4(0.f, 0.f, 0.f, 0.f);
}

// x_new = relu(selfY + self_b + agg/max(deg,1)); optional mask; optionally
// re-zeroes agg in place for the next layer (saves a zero launch).
__launch_bounds__(256)
__global__ void update_kernel(const float* __restrict__ y0,
                              float* __restrict__ agg,
                              const float* __restrict__ deg,
                              const float* __restrict__ selfb,
                              const int*   __restrict__ mask,
                              float* __restrict__ out,
                              int apply_mask, int rezero)
{
    const int idx = blockIdx.x * 256 + threadIdx.x;
    const int v  = idx >> 5;
    const int h4 = idx & 31;

    const float4 y = ((const float4*)y0)[idx];
    const float4 a = ((float4*)agg)[idx];
    const float4 b = ((const float4*)selfb)[h4];
    const float id = 1.0f / fmaxf(deg[v], 1.0f);
    float m = 1.0f;
    if (apply_mask) m = (float)mask[v];

    float4 r;
    r.x = fmaxf(y.x + b.x + a.x * id, 0.0f) * m;
    r.y = fmaxf(y.y + b.y + a.y * id, 0.0f) * m;
    r.z = fmaxf(y.z + b.z + a.z * id, 0.0f) * m;
    r.w = fmaxf(y.w + b.w + a.w * id, 0.0f) * m;
    ((float4*)out)[idx] = r;
    if (rezero) ((float4*)agg)[idx] = make_float4(0.f, 0.f, 0.f, 0.f);
}

extern "C" void kernel_launch(void* const* d_in, const int* in_sizes, int n_in,
                              void* d_out, int out_size)
{
    const int*   cid   = (const int*)  d_in[0];
    const int*   kid   = (const int*)  d_in[1];
    const int*   mask  = (const int*)  d_in[2];
    const int*   eidx  = (const int*)  d_in[3];
    const int*   et    = (const int*)  d_in[4];
    const float* cemb  = (const float*)d_in[5];
    const float* kemb  = (const float*)d_in[6];
    const float* projW = (const float*)d_in[7];
    const float* projb = (const float*)d_in[8];
    const float* selfW = (const float*)d_in[9];
    const float* selfb = (const float*)d_in[10];
    const float* relW  = (const float*)d_in[11];

    const int* src = eidx;
    const int* dst = eidx + NE;

    float *x, *x2, *agg, *deg, *y;
    cudaGetSymbolAddress((void**)&x,   g_x);
    cudaGetSymbolAddress((void**)&x2,  g_x2);
    cudaGetSymbolAddress((void**)&agg, g_agg);
    cudaGetSymbolAddress((void**)&deg, g_deg);
    cudaGetSymbolAddress((void**)&y,   g_y);

    const int use_tc = g_has_tc;
    if (use_tc) {
        cudaFuncSetAttribute(tgemm_proj, cudaFuncAttributeMaxDynamicSharedMemorySize, SMEM_TOTAL0);
        cudaFuncSetAttribute(tgemm9,     cudaFuncAttributeMaxDynamicSharedMemorySize, SMEM_TOTAL9);
    }

    // Degrees + zero agg (layer 0)
    zero_kernel<<<(NV / 4 + 255) / 256, 256>>>(deg, NV / 4);
    deg_kernel<<<NE / 256, 256>>>(dst, deg);
    zero_kernel<<<(NV * Hd / 4) / 256, 256>>>(agg, NV * Hd / 4);

    // Input embedding + projection -> x
    if (use_tc)
        tgemm_proj<<<NV / 128, 128, SMEM_TOTAL0>>>(cid, kid, cemb, kemb, projW, projb, x);
    else
        gemm_fb<0><<<dim3(NV / 128, 1), 256>>>(nullptr, cid, kid, cemb, kemb,
                                               nullptr, projW, projb, x);

    float* cur = x;
    float* nxt = x2;
    for (int l = 0; l < NL; l++) {
        // Y[0] = x @ self_W[l]^T ; Y[1+r] = x @ rel_W[l,r]^T
        if (use_tc)
            tgemm9<<<NV / 128, 128, SMEM_TOTAL9>>>(
                cur, selfW + (size_t)l * Hd * Hd, relW + (size_t)l * NR * Hd * Hd, y);
        else
            gemm_fb<1><<<dim3(NV / 128, NR + 1), 256>>>(
                cur, nullptr, nullptr, nullptr, nullptr,
                selfW + (size_t)l * Hd * Hd, relW + (size_t)l * NR * Hd * Hd,
                nullptr, y);

        scatter_kernel<<<NE / 8, 256>>>(src, dst, et, y, agg);

        float* outp = (l == NL - 1) ? (float*)d_out : nxt;
        update_kernel<<<(NV * Hd / 4) / 256, 256>>>(
            y, agg, deg, selfb + (size_t)l * Hd, mask, outp,
            (l == NL - 1) ? 1 : 0, (l == NL - 1) ? 0 : 1);
        float* tmp = cur; cur = nxt; nxt = tmp;
    }
}

// round 6
// speedup vs baseline: 3.3040x; 1.1431x over previous
#include <cuda_runtime.h>
#include <cuda_bf16.h>
#include <cstdint>

// ---------------------------------------------------------------------------
// Arch feature gate: tcgen05 exists only on sm_103a / family 103f.
// ---------------------------------------------------------------------------
#if defined(__CUDA_ARCH__) && (defined(__CUDA_ARCH_FEAT_SM103_ALL) || \
    (defined(__CUDA_ARCH_FAMILY_SPECIFIC__) && (__CUDA_ARCH_FAMILY_SPECIFIC__ == 1030)))
#define TC_OK 1
#else
#define TC_OK 0
#endif

// Problem constants (fixed by dataset)
constexpr int NV = 32768;          // B*N nodes
constexpr int Hd = 128;            // hidden
constexpr int NE = 524288;         // edges
constexpr int NR = 8;              // relations
constexpr int NL = 2;              // layers
constexpr int NSLAB = NR + 1;      // 9: slab 0 = self, 1..8 = relations

// Scratch (static device globals; no allocation at runtime)
__device__ float g_x  [(size_t)NV * Hd];
__device__ float g_x2 [(size_t)NV * Hd];
__device__ float g_y  [(size_t)NSLAB * NV * Hd];
__device__ int   g_hist    [NV + 2];
__device__ int   g_rowstart[NV + 2];
__device__ int   g_cursor  [NV];
__device__ int   g_sorted  [NE];     // ((type+1)<<15) | src, grouped by dst
__device__ int   g_tc_flag;

// ---------------------------------------------------------------------------
// Capability probe (runs at static-init, outside graph capture)
// ---------------------------------------------------------------------------
__global__ void probe_kernel() { g_tc_flag = TC_OK; }

static int detect_tc() {
    int v = 0;
    probe_kernel<<<1, 1>>>();
    cudaMemcpyFromSymbol(&v, g_tc_flag, sizeof(int));
    return v;
}
static const int g_has_tc = detect_tc();

// ---------------------------------------------------------------------------
// PTX helpers
// ---------------------------------------------------------------------------
__device__ __forceinline__ uint32_t smem_u32(const void* p) {
    uint32_t a;
    asm("{ .reg .u64 t; cvta.to.shared.u64 t, %1; cvt.u32.u64 %0, t; }" : "=r"(a) : "l"(p));
    return a;
}
__device__ __forceinline__ uint32_t elect_one() {
    uint32_t p;
    asm volatile("{\n\t.reg .pred p;\n\telect.sync _|p, 0xFFFFFFFF;\n\tselp.b32 %0, 1, 0, p;\n\t}" : "=r"(p));
    return p;
}
__device__ __forceinline__ uint32_t f2tf32(float f) {
    uint32_t u;
    asm("cvt.rna.tf32.f32 %0, %1;" : "=r"(u) : "f"(f));
    return u;
}

#if TC_OK
#define TC_ALLOC(sm, n)   asm volatile("tcgen05.alloc.cta_group::1.sync.aligned.shared::cta.b32 [%0], %1;" :: "r"(sm), "r"(n) : "memory")
#define TC_DEALLOC(t, n)  asm volatile("tcgen05.dealloc.cta_group::1.sync.aligned.b32 %0, %1;" :: "r"(t), "r"(n))
#define TC_RELINQ()       asm volatile("tcgen05.relinquish_alloc_permit.cta_group::1.sync.aligned;")
#define TC_COMMIT(mb)     asm volatile("tcgen05.commit.cta_group::1.mbarrier::arrive::one.shared::cluster.b64 [%0];" :: "r"(mb) : "memory")
#define TC_WAIT_LD()      asm volatile("tcgen05.wait::ld.sync.aligned;" ::: "memory")
#define TC_FENCE_AFTER()  asm volatile("tcgen05.fence::after_thread_sync;" ::: "memory")
#define TC_FENCE_BEFORE() asm volatile("tcgen05.fence::before_thread_sync;" ::: "memory")
#endif

#define MBAR_INIT(mb, c)  asm volatile("mbarrier.init.shared.b64 [%0], %1;" :: "r"(mb), "r"(c) : "memory")
#define MBAR_INVAL(mb)    asm volatile("mbarrier.inval.shared.b64 [%0];" :: "r"(mb) : "memory")

__device__ __forceinline__ void mbar_wait(uint32_t mb, uint32_t parity) {
    asm volatile(
        "{\n\t.reg .pred P1;\n\t"
        "WL_%=:\n\t"
        "mbarrier.try_wait.parity.acquire.cta.shared::cta.b64 P1, [%0], %1, 0x989680;\n\t"
        "@P1 bra.uni WD_%=;\n\t"
        "bra.uni WL_%=;\n\t"
        "WD_%=:\n\t}"
        :: "r"(mb), "r"(parity) : "memory");
}

#if TC_OK
__device__ __forceinline__ void mma_tf32_ss(uint32_t d, uint64_t ad, uint64_t bd,
                                            uint32_t idesc, uint32_t en) {
    asm volatile(
        "{\n\t.reg .pred p;\n\tsetp.ne.u32 p, %5, 0;\n\t"
        "tcgen05.mma.cta_group::1.kind::tf32 [%0], %1, %2, %3, {%4, %4, %4, %4}, p;\n\t}"
        :: "r"(d), "l"(ad), "l"(bd), "r"(idesc), "r"(0u), "r"(en) : "memory");
}

__device__ __forceinline__ void ldtm_x32(uint32_t* r, uint32_t addr) {
    asm volatile(
        "tcgen05.ld.sync.aligned.32x32b.x32.b32 "
        "{%0,%1,%2,%3,%4,%5,%6,%7,%8,%9,%10,%11,%12,%13,%14,%15,"
        "%16,%17,%18,%19,%20,%21,%22,%23,%24,%25,%26,%27,%28,%29,%30,%31}, [%32];"
        : "=r"(r[0]), "=r"(r[1]), "=r"(r[2]), "=r"(r[3]), "=r"(r[4]), "=r"(r[5]), "=r"(r[6]), "=r"(r[7]),
          "=r"(r[8]), "=r"(r[9]), "=r"(r[10]), "=r"(r[11]), "=r"(r[12]), "=r"(r[13]), "=r"(r[14]), "=r"(r[15]),
          "=r"(r[16]), "=r"(r[17]), "=r"(r[18]), "=r"(r[19]), "=r"(r[20]), "=r"(r[21]), "=r"(r[22]), "=r"(r[23]),
          "=r"(r[24]), "=r"(r[25]), "=r"(r[26]), "=r"(r[27]), "=r"(r[28]), "=r"(r[29]), "=r"(r[30]), "=r"(r[31])
        : "r"(addr));
}
#endif

// SW128 K-major blocked-atom layout for a 128x128 fp32 tile.
__device__ __forceinline__ uint32_t tile_off(int row, int k) {
    uint32_t off = ((uint32_t)((k >> 5) * 16 + (row >> 3)) << 10)
                 + ((uint32_t)(row & 7) << 7) + ((uint32_t)(k & 31) << 2);
    return off ^ ((off >> 3) & 0x70);
}

// smem descriptor: SW128, version=1, LBO=1, SBO=64
__device__ __forceinline__ uint64_t make_desc(uint32_t base) {
    const uint64_t BASE = (uint64_t(2) << 61) | (uint64_t(1) << 46)
                        | (uint64_t(64) << 32) | (uint64_t(1) << 16);
    return BASE | ((uint64_t)(base >> 4) & 0x3FFF);
}

constexpr uint32_t IDESC_TF32 = (1u << 4) | (2u << 7) | (2u << 10) | (16u << 17) | (8u << 24);

// Dynamic SMEM layout
constexpr int SMEM_TMEM = 0;
constexpr int SMEM_MB0  = 8;
constexpr int SMEM_MB1  = 16;
constexpr int SMEM_A    = 1024;
constexpr int SMEM_W0   = SMEM_A  + 65536;
constexpr int SMEM_W1   = SMEM_W0 + 65536;
constexpr int SMEM_TOTAL9 = SMEM_W1 + 65536 + 128;
constexpr int SMEM_TOTAL0 = SMEM_W0 + 65536 + 128;

// ---------------------------------------------------------------------------
// Projection GEMM: x = (cemb[cid]+kemb[kid]) @ projW^T + b
// ---------------------------------------------------------------------------
__global__ void __launch_bounds__(128, 1)
tgemm_proj(const int* __restrict__ cid, const int* __restrict__ kid,
           const float* __restrict__ cemb, const float* __restrict__ kemb,
           const float* __restrict__ W, const float* __restrict__ bias,
           float* __restrict__ Cout)
{
#if TC_OK
    extern __shared__ char smem[];
    const uint32_t sb = smem_u32(smem);
    const int tid = threadIdx.x;
    const int wid = tid >> 5;
    const int lid = tid & 31;
    const int vbase = blockIdx.x * 128;
    float* C = Cout + (size_t)vbase * Hd;

    if (wid == 0) TC_ALLOC(sb + SMEM_TMEM, 128);
    else          TC_RELINQ();
    __syncthreads();
    uint32_t tmem;
    asm volatile("ld.shared.b32 %0, [%1];" : "=r"(tmem) : "r"(sb + SMEM_TMEM));

    {
        const float4* ar = (const float4*)(cemb + (size_t)cid[vbase + tid] * Hd);
        const float4* kr = (const float4*)(kemb + (size_t)kid[vbase + tid] * Hd);
        const float4* wr = (const float4*)(W + (size_t)tid * Hd);
#pragma unroll
        for (int c4 = 0; c4 < 32; c4++) {
            float4 a = ar[c4];
            const float4 k = kr[c4];
            a.x += k.x; a.y += k.y; a.z += k.z; a.w += k.w;
            *(uint4*)(smem + SMEM_A + tile_off(tid, c4 * 4)) =
                make_uint4(f2tf32(a.x), f2tf32(a.y), f2tf32(a.z), f2tf32(a.w));
            const float4 w = wr[c4];
            *(uint4*)(smem + SMEM_W0 + tile_off(tid, c4 * 4)) =
                make_uint4(f2tf32(w.x), f2tf32(w.y), f2tf32(w.z), f2tf32(w.w));
        }
    }
    asm volatile("fence.proxy.async.shared::cta;" ::: "memory");
    TC_FENCE_BEFORE();
    __syncthreads();

    if (wid == 0) {
        if (elect_one()) MBAR_INIT(sb + SMEM_MB0, 1);
        __syncwarp();
        TC_FENCE_AFTER();
        const uint64_t ad = make_desc(sb + SMEM_A);
        const uint64_t bd = make_desc(sb + SMEM_W0);
        if (elect_one()) {
#pragma unroll
            for (int s = 0; s < 16; s++) {
                const uint64_t off = (uint64_t)((s >> 2) * 1024 + (s & 3) * 2);
                mma_tf32_ss(tmem, ad + off, bd + off, IDESC_TF32, s > 0 ? 1u : 0u);
            }
            TC_COMMIT(sb + SMEM_MB0);
        }
    }
    __syncthreads();
    mbar_wait(sb + SMEM_MB0, 0);
    TC_FENCE_AFTER();

    const int row = wid * 32 + lid;
    float* crow = C + (size_t)row * Hd;
#pragma unroll
    for (int ch = 0; ch < 4; ch++) {
        uint32_t d[32];
        ldtm_x32(d, tmem + ch * 32);
        TC_WAIT_LD();
#pragma unroll
        for (int q = 0; q < 8; q++) {
            *(float4*)(crow + ch * 32 + q * 4) = make_float4(
                __uint_as_float(d[q*4+0]) + bias[ch*32 + q*4+0],
                __uint_as_float(d[q*4+1]) + bias[ch*32 + q*4+1],
                __uint_as_float(d[q*4+2]) + bias[ch*32 + q*4+2],
                __uint_as_float(d[q*4+3]) + bias[ch*32 + q*4+3]);
        }
    }
    TC_FENCE_BEFORE();
    __syncthreads();
    if (wid == 0) {
        if (elect_one()) MBAR_INVAL(sb + SMEM_MB0);
        TC_DEALLOC(tmem, 128);
    }
#endif
}

// ---------------------------------------------------------------------------
// 9-slab GEMM: one CTA = one 128-row x-block; A loaded once; 9 weights stream
// through double-buffered smem; D ping-pongs between two TMEM buffers.
// ---------------------------------------------------------------------------
__global__ void __launch_bounds__(128, 1)
tgemm9(const float* __restrict__ Asrc,
       const float* __restrict__ selfW,
       const float* __restrict__ relW,
       float* __restrict__ Yout)
{
#if TC_OK
    extern __shared__ char smem[];
    const uint32_t sb = smem_u32(smem);
    const int tid = threadIdx.x;
    const int wid = tid >> 5;
    const int lid = tid & 31;
    const int vbase = blockIdx.x * 128;

    if (wid == 0) TC_ALLOC(sb + SMEM_TMEM, 256);
    else          TC_RELINQ();
    __syncthreads();
    uint32_t tmem;
    asm volatile("ld.shared.b32 %0, [%1];" : "=r"(tmem) : "r"(sb + SMEM_TMEM));

    if (tid == 0) {
        MBAR_INIT(sb + SMEM_MB0, 1);
        MBAR_INIT(sb + SMEM_MB1, 1);
    }

    {
        const float4* ar = (const float4*)(Asrc + (size_t)(vbase + tid) * Hd);
#pragma unroll
        for (int c4 = 0; c4 < 32; c4++) {
            const float4 a = ar[c4];
            *(uint4*)(smem + SMEM_A + tile_off(tid, c4 * 4)) =
                make_uint4(f2tf32(a.x), f2tf32(a.y), f2tf32(a.z), f2tf32(a.w));
        }
    }
    {
        const float4* wr = (const float4*)(selfW + (size_t)tid * Hd);
#pragma unroll
        for (int c4 = 0; c4 < 32; c4++) {
            const float4 w = wr[c4];
            *(uint4*)(smem + SMEM_W0 + tile_off(tid, c4 * 4)) =
                make_uint4(f2tf32(w.x), f2tf32(w.y), f2tf32(w.z), f2tf32(w.w));
        }
    }
    asm volatile("fence.proxy.async.shared::cta;" ::: "memory");
    TC_FENCE_BEFORE();
    __syncthreads();

    const uint64_t ad = make_desc(sb + SMEM_A);
    const int row = wid * 32 + lid;

    for (int j = 0; j < NSLAB; j++) {
        const int buf = j & 1;
        const uint32_t dtm = tmem + buf * 128;

        if (wid == 0) {
            TC_FENCE_AFTER();
            const uint64_t bd = make_desc(sb + (buf ? SMEM_W1 : SMEM_W0));
            if (elect_one()) {
#pragma unroll
                for (int s = 0; s < 16; s++) {
                    const uint64_t off = (uint64_t)((s >> 2) * 1024 + (s & 3) * 2);
                    mma_tf32_ss(dtm, ad + off, bd + off, IDESC_TF32, s > 0 ? 1u : 0u);
                }
                TC_COMMIT(sb + (buf ? SMEM_MB1 : SMEM_MB0));
            }
        }

        if (j + 1 < NSLAB) {
            const float* Wn = relW + (size_t)j * Hd * Hd;
            const float4* wr = (const float4*)(Wn + (size_t)tid * Hd);
            char* wb = smem + ((j + 1) & 1 ? SMEM_W1 : SMEM_W0);
#pragma unroll
            for (int c4 = 0; c4 < 32; c4++) {
                const float4 w = wr[c4];
                *(uint4*)(wb + tile_off(tid, c4 * 4)) =
                    make_uint4(f2tf32(w.x), f2tf32(w.y), f2tf32(w.z), f2tf32(w.w));
            }
        }

        mbar_wait(sb + (buf ? SMEM_MB1 : SMEM_MB0), (j >> 1) & 1);
        TC_FENCE_AFTER();

        float* crow = Yout + ((size_t)j * NV + (size_t)(vbase + row)) * Hd;
#pragma unroll
        for (int ch = 0; ch < 4; ch++) {
            uint32_t d[32];
            ldtm_x32(d, dtm + ch * 32);
            TC_WAIT_LD();
#pragma unroll
            for (int q = 0; q < 8; q++) {
                *(float4*)(crow + ch * 32 + q * 4) = make_float4(
                    __uint_as_float(d[q*4+0]), __uint_as_float(d[q*4+1]),
                    __uint_as_float(d[q*4+2]), __uint_as_float(d[q*4+3]));
            }
        }
        TC_FENCE_BEFORE();
        asm volatile("fence.proxy.async.shared::cta;" ::: "memory");
        __syncthreads();
    }

    if (tid == 0) { MBAR_INVAL(sb + SMEM_MB0); MBAR_INVAL(sb + SMEM_MB1); }
    __syncthreads();
    if (wid == 0) TC_DEALLOC(tmem, 256);
#endif
}

// ---------------------------------------------------------------------------
// Fallback SIMT fp32 GEMM — used only if tcgen05 unavailable.
// ---------------------------------------------------------------------------
template <int MODE>
__launch_bounds__(256)
__global__ void gemm_fb(const float* __restrict__ Asrc,
                        const int*   __restrict__ cid,
                        const int*   __restrict__ kid,
                        const float* __restrict__ cemb,
                        const float* __restrict__ kemb,
                        const float* __restrict__ selfW,
                        const float* __restrict__ relW,
                        const float* __restrict__ bias,
                        float* __restrict__ Cout)
{
    __shared__ float As[32][132];
    __shared__ float Ws[32][132];
    __shared__ int   s_cid[128];
    __shared__ int   s_kid[128];

    const int tid = threadIdx.x;
    const int tx = tid & 15;
    const int ty = tid >> 4;
    const int vbase = blockIdx.x * 128;

    const float* W;
    float* C;
    if (MODE == 0) {
        W = relW;
        C = Cout + (size_t)vbase * Hd;
    } else {
        const int j = blockIdx.y;
        W = (j == 0) ? selfW : (relW + (size_t)(j - 1) * Hd * Hd);
        C = Cout + ((size_t)j * NV + (size_t)vbase) * Hd;
    }

    if (MODE == 0) {
        if (tid < 128) {
            s_cid[tid] = cid[vbase + tid];
            s_kid[tid] = kid[vbase + tid];
        }
        __syncthreads();
    }

    float acc[8][8];
#pragma unroll
    for (int i = 0; i < 8; i++)
#pragma unroll
        for (int j = 0; j < 8; j++) acc[i][j] = 0.0f;

#pragma unroll
    for (int kc = 0; kc < Hd; kc += 32) {
#pragma unroll
        for (int rep = 0; rep < 4; rep++) {
            const int i   = tid + rep * 256;
            const int r   = i >> 3;
            const int c4  = i & 7;
            float4 a;
            if (MODE == 0) {
                const float4 av = ((const float4*)(cemb + (size_t)s_cid[r] * Hd + kc))[c4];
                const float4 kv = ((const float4*)(kemb + (size_t)s_kid[r] * Hd + kc))[c4];
                a = make_float4(av.x + kv.x, av.y + kv.y, av.z + kv.z, av.w + kv.w);
            } else {
                a = *(const float4*)(Asrc + (size_t)(vbase + r) * Hd + kc + c4 * 4);
            }
            As[c4 * 4 + 0][r] = a.x; As[c4 * 4 + 1][r] = a.y;
            As[c4 * 4 + 2][r] = a.z; As[c4 * 4 + 3][r] = a.w;
            const float4 w = *(const float4*)(W + (size_t)r * Hd + kc + c4 * 4);
            Ws[c4 * 4 + 0][r] = w.x; Ws[c4 * 4 + 1][r] = w.y;
            Ws[c4 * 4 + 2][r] = w.z; Ws[c4 * 4 + 3][r] = w.w;
        }
        __syncthreads();

#pragma unroll
        for (int k = 0; k < 32; k++) {
            const float4 a0 = *(const float4*)&As[k][ty * 8];
            const float4 a1 = *(const float4*)&As[k][ty * 8 + 4];
            const float4 w0 = *(const float4*)&Ws[k][tx * 8];
            const float4 w1 = *(const float4*)&Ws[k][tx * 8 + 4];
            const float a[8] = {a0.x, a0.y, a0.z, a0.w, a1.x, a1.y, a1.z, a1.w};
            const float w[8] = {w0.x, w0.y, w0.z, w0.w, w1.x, w1.y, w1.z, w1.w};
#pragma unroll
            for (int i = 0; i < 8; i++)
#pragma unroll
                for (int j = 0; j < 8; j++) acc[i][j] += a[i] * w[j];
        }
        __syncthreads();
    }

    float b0[8];
    if (MODE == 0) {
#pragma unroll
        for (int j = 0; j < 8; j++) b0[j] = bias[tx * 8 + j];
    }
#pragma unroll
    for (int i = 0; i < 8; i++) {
        const int r = ty * 8 + i;
        float4 v0, v1;
        if (MODE == 0) {
            v0 = make_float4(acc[i][0] + b0[0], acc[i][1] + b0[1],
                             acc[i][2] + b0[2], acc[i][3] + b0[3]);
            v1 = make_float4(acc[i][4] + b0[4], acc[i][5] + b0[5],
                             acc[i][6] + b0[6], acc[i][7] + b0[7]);
        } else {
            v0 = make_float4(acc[i][0], acc[i][1], acc[i][2], acc[i][3]);
            v1 = make_float4(acc[i][4], acc[i][5], acc[i][6], acc[i][7]);
        }
        *(float4*)(C + (size_t)r * Hd + tx * 8)     = v0;
        *(float4*)(C + (size_t)r * Hd + tx * 8 + 4) = v1;
    }
}

// ---------------------------------------------------------------------------
// CSR build: histogram -> exclusive scan (1 CTA) -> placement
// ---------------------------------------------------------------------------
__launch_bounds__(256)
__global__ void zero_int_kernel(int* __restrict__ p, int n)
{
    const int i = blockIdx.x * 256 + threadIdx.x;
    if (i < n) p[i] = 0;
}

__launch_bounds__(256)
__global__ void hist_kernel(const int* __restrict__ dst, int* __restrict__ hist)
{
    const int e = blockIdx.x * 256 + threadIdx.x;
    atomicAdd(&hist[dst[e]], 1);
}

__launch_bounds__(1024)
__global__ void scan_kernel(const int* __restrict__ hist, int* __restrict__ rowstart)
{
    __shared__ int part[1024];
    const int t = threadIdx.x;
    const int base = t * 32;
    int local[32];
    int sum = 0;
#pragma unroll
    for (int i = 0; i < 32; i++) { local[i] = sum; sum += hist[base + i]; }
    part[t] = sum;
    __syncthreads();
    // Hillis-Steele inclusive scan over 1024 partials
    for (int d = 1; d < 1024; d <<= 1) {
        int v = part[t];
        int add = (t >= d) ? part[t - d] : 0;
        __syncthreads();
        part[t] = v + add;
        __syncthreads();
    }
    const int excl = part[t] - sum;
#pragma unroll
    for (int i = 0; i < 32; i++) rowstart[base + i] = excl + local[i];
    if (t == 1023) rowstart[NV] = excl + sum;
}

__launch_bounds__(256)
__global__ void place_kernel(const int* __restrict__ src,
                             const int* __restrict__ dst,
                             const int* __restrict__ et,
                             int* __restrict__ cursor,
                             int* __restrict__ sorted)
{
    const int e = blockIdx.x * 256 + threadIdx.x;
    const int d = dst[e];
    const int pos = atomicAdd(&cursor[d], 1);
    sorted[pos] = ((et[e] + 1) << 15) | src[e];
}

// ---------------------------------------------------------------------------
// Fused gather + update: one warp per dst node.
// out[v] = relu(Y[0][v] + self_b + (sum_{in-edges} Y[slab][src]) / max(deg,1)) [* mask]
// ---------------------------------------------------------------------------
__launch_bounds__(256)
__global__ void gather_update_kernel(const int* __restrict__ rowstart,
                                     const int* __restrict__ sorted,
                                     const float* __restrict__ y,
                                     const float* __restrict__ selfb,
                                     const int*  __restrict__ mask,
                                     float* __restrict__ out,
                                     int apply_mask)
{
    const int v    = blockIdx.x * 8 + (threadIdx.x >> 5);
    const int lane = threadIdx.x & 31;
    const int s = rowstart[v];
    const int e = rowstart[v + 1];

    float4 acc = make_float4(0.f, 0.f, 0.f, 0.f);
    int i = s;
    for (; i + 3 < e; i += 4) {
        const int p0 = sorted[i], p1 = sorted[i + 1], p2 = sorted[i + 2], p3 = sorted[i + 3];
        const float4 a0 = ((const float4*)(y + (size_t)p0 * Hd))[lane];
        const float4 a1 = ((const float4*)(y + (size_t)p1 * Hd))[lane];
        const float4 a2 = ((const float4*)(y + (size_t)p2 * Hd))[lane];
        const float4 a3 = ((const float4*)(y + (size_t)p3 * Hd))[lane];
        acc.x += a0.x + a1.x + a2.x + a3.x;
        acc.y += a0.y + a1.y + a2.y + a3.y;
        acc.z += a0.z + a1.z + a2.z + a3.z;
        acc.w += a0.w + a1.w + a2.w + a3.w;
    }
    for (; i < e; i++) {
        const int p = sorted[i];
        const float4 a = ((const float4*)(y + (size_t)p * Hd))[lane];
        acc.x += a.x; acc.y += a.y; acc.z += a.z; acc.w += a.w;
    }

    const float id = 1.0f / fmaxf((float)(e - s), 1.0f);
    const float4 yv = ((const float4*)(y + (size_t)v * Hd))[lane];
    const float4 b  = ((const float4*)selfb)[lane];
    float m = 1.0f;
    if (apply_mask) m = (float)mask[v];

    float4 r;
    r.x = fmaxf(yv.x + b.x + acc.x * id, 0.0f) * m;
    r.y = fmaxf(yv.y + b.y + acc.y * id, 0.0f) * m;
    r.z = fmaxf(yv.z + b.z + acc.z * id, 0.0f) * m;
    r.w = fmaxf(yv.w + b.w + acc.w * id, 0.0f) * m;
    ((float4*)(out + (size_t)v * Hd))[lane] = r;
}

extern "C" void kernel_launch(void* const* d_in, const int* in_sizes, int n_in,
                              void* d_out, int out_size)
{
    const int*   cid   = (const int*)  d_in[0];
    const int*   kid   = (const int*)  d_in[1];
    const int*   mask  = (const int*)  d_in[2];
    const int*   eidx  = (const int*)  d_in[3];
    const int*   et    = (const int*)  d_in[4];
    const float* cemb  = (const float*)d_in[5];
    const float* kemb  = (const float*)d_in[6];
    const float* projW = (const float*)d_in[7];
    const float* projb = (const float*)d_in[8];
    const float* selfW = (const float*)d_in[9];
    const float* selfb = (const float*)d_in[10];
    const float* relW  = (const float*)d_in[11];

    const int* src = eidx;
    const int* dst = eidx + NE;

    float *x, *x2, *y;
    int *hist, *rowstart, *cursor, *sorted;
    cudaGetSymbolAddress((void**)&x,        g_x);
    cudaGetSymbolAddress((void**)&x2,       g_x2);
    cudaGetSymbolAddress((void**)&y,        g_y);
    cudaGetSymbolAddress((void**)&hist,     g_hist);
    cudaGetSymbolAddress((void**)&rowstart, g_rowstart);
    cudaGetSymbolAddress((void**)&cursor,   g_cursor);
    cudaGetSymbolAddress((void**)&sorted,   g_sorted);

    const int use_tc = g_has_tc;
    if (use_tc) {
        cudaFuncSetAttribute(tgemm_proj, cudaFuncAttributeMaxDynamicSharedMemorySize, SMEM_TOTAL0);
        cudaFuncSetAttribute(tgemm9,     cudaFuncAttributeMaxDynamicSharedMemorySize, SMEM_TOTAL9);
    }

    // --- CSR build (once per launch) ---
    zero_int_kernel<<<(NV + 256) / 256, 256>>>(hist, NV + 1);
    hist_kernel<<<NE / 256, 256>>>(dst, hist);
    scan_kernel<<<1, 1024>>>(hist, rowstart);
    cudaMemcpyAsync(cursor, rowstart, NV * sizeof(int), cudaMemcpyDeviceToDevice);
    place_kernel<<<NE / 256, 256>>>(src, dst, et, cursor, sorted);

    // --- input embedding + projection -> x ---
    if (use_tc)
        tgemm_proj<<<NV / 128, 128, SMEM_TOTAL0>>>(cid, kid, cemb, kemb, projW, projb, x);
    else
        gemm_fb<0><<<dim3(NV / 128, 1), 256>>>(nullptr, cid, kid, cemb, kemb,
                                               nullptr, projW, projb, x);

    float* cur = x;
    float* nxt = x2;
    for (int l = 0; l < NL; l++) {
        // Y[0] = x @ self_W[l]^T ; Y[1+r] = x @ rel_W[l,r]^T
        if (use_tc)
            tgemm9<<<NV / 128, 128, SMEM_TOTAL9>>>(
                cur, selfW + (size_t)l * Hd * Hd, relW + (size_t)l * NR * Hd * Hd, y);
        else
            gemm_fb<1><<<dim3(NV / 128, NR + 1), 256>>>(
                cur, nullptr, nullptr, nullptr, nullptr,
                selfW + (size_t)l * Hd * Hd, relW + (size_t)l * NR * Hd * Hd,
                nullptr, y);

        float* outp = (l == NL - 1) ? (float*)d_out : nxt;
        gather_update_kernel<<<NV / 8, 256>>>(rowstart, sorted, y, selfb + (size_t)l * Hd,
                                              mask, outp, (l == NL - 1) ? 1 : 0);
        float* tmp = cur; cur = nxt; nxt = tmp;
    }
}

// round 7
// speedup vs baseline: 3.8369x; 1.1613x over previous
#include <cuda_runtime.h>
#include <cuda_bf16.h>
#include <cstdint>

// ---------------------------------------------------------------------------
// Arch feature gate: tcgen05 exists only on sm_103a / family 103f.
// ---------------------------------------------------------------------------
#if defined(__CUDA_ARCH__) && (defined(__CUDA_ARCH_FEAT_SM103_ALL) || \
    (defined(__CUDA_ARCH_FAMILY_SPECIFIC__) && (__CUDA_ARCH_FAMILY_SPECIFIC__ == 1030)))
#define TC_OK 1
#else
#define TC_OK 0
#endif

// Problem constants (fixed by dataset)
constexpr int NV = 32768;          // B*N nodes
constexpr int Hd = 128;            // hidden
constexpr int NE = 524288;         // edges
constexpr int NR = 8;              // relations
constexpr int NL = 2;              // layers
constexpr int NSLAB = NR + 1;      // 9: slab 0 = self, 1..8 = relations

// Scratch (static device globals; no allocation at runtime)
__device__ float g_x  [(size_t)NV * Hd];
__device__ float g_x2 [(size_t)NV * Hd];
__device__ float g_y  [(size_t)NSLAB * NV * Hd];
__device__ __align__(16) int g_hist    [NV + 4];
__device__ __align__(16) int g_rowstart[NV + 4];
__device__ __align__(16) int g_cursor  [NV + 4];
__device__ int   g_sorted  [NE];     // ((type+1)<<15) | src, grouped by dst
__device__ int   g_tc_flag;

// ---------------------------------------------------------------------------
// Static-init setup: capability probe + side stream/events for fork-join
// (all outside graph capture; no device memory allocation)
// ---------------------------------------------------------------------------
__global__ void probe_kernel() { g_tc_flag = TC_OK; }

static cudaStream_t s_side;
static cudaEvent_t  s_ev_fork, s_ev_join;

static int setup_once() {
    int v = 0;
    probe_kernel<<<1, 1>>>();
    cudaMemcpyFromSymbol(&v, g_tc_flag, sizeof(int));
    cudaStreamCreateWithFlags(&s_side, cudaStreamNonBlocking);
    cudaEventCreateWithFlags(&s_ev_fork, cudaEventDisableTiming);
    cudaEventCreateWithFlags(&s_ev_join, cudaEventDisableTiming);
    return v;
}
static const int g_has_tc = setup_once();

// ---------------------------------------------------------------------------
// PTX helpers
// ---------------------------------------------------------------------------
__device__ __forceinline__ uint32_t smem_u32(const void* p) {
    uint32_t a;
    asm("{ .reg .u64 t; cvta.to.shared.u64 t, %1; cvt.u32.u64 %0, t; }" : "=r"(a) : "l"(p));
    return a;
}
__device__ __forceinline__ uint32_t elect_one() {
    uint32_t p;
    asm volatile("{\n\t.reg .pred p;\n\telect.sync _|p, 0xFFFFFFFF;\n\tselp.b32 %0, 1, 0, p;\n\t}" : "=r"(p));
    return p;
}
__device__ __forceinline__ uint32_t f2tf32(float f) {
    uint32_t u;
    asm("cvt.rna.tf32.f32 %0, %1;" : "=r"(u) : "f"(f));
    return u;
}

#if TC_OK
#define TC_ALLOC(sm, n)   asm volatile("tcgen05.alloc.cta_group::1.sync.aligned.shared::cta.b32 [%0], %1;" :: "r"(sm), "r"(n) : "memory")
#define TC_DEALLOC(t, n)  asm volatile("tcgen05.dealloc.cta_group::1.sync.aligned.b32 %0, %1;" :: "r"(t), "r"(n))
#define TC_RELINQ()       asm volatile("tcgen05.relinquish_alloc_permit.cta_group::1.sync.aligned;")
#define TC_COMMIT(mb)     asm volatile("tcgen05.commit.cta_group::1.mbarrier::arrive::one.shared::cluster.b64 [%0];" :: "r"(mb) : "memory")
#define TC_WAIT_LD()      asm volatile("tcgen05.wait::ld.sync.aligned;" ::: "memory")
#define TC_FENCE_AFTER()  asm volatile("tcgen05.fence::after_thread_sync;" ::: "memory")
#define TC_FENCE_BEFORE() asm volatile("tcgen05.fence::before_thread_sync;" ::: "memory")
#endif

#define MBAR_INIT(mb, c)  asm volatile("mbarrier.init.shared.b64 [%0], %1;" :: "r"(mb), "r"(c) : "memory")
#define MBAR_INVAL(mb)    asm volatile("mbarrier.inval.shared.b64 [%0];" :: "r"(mb) : "memory")

__device__ __forceinline__ void mbar_wait(uint32_t mb, uint32_t parity) {
    asm volatile(
        "{\n\t.reg .pred P1;\n\t"
        "WL_%=:\n\t"
        "mbarrier.try_wait.parity.acquire.cta.shared::cta.b64 P1, [%0], %1, 0x989680;\n\t"
        "@P1 bra.uni WD_%=;\n\t"
        "bra.uni WL_%=;\n\t"
        "WD_%=:\n\t}"
        :: "r"(mb), "r"(parity) : "memory");
}

#if TC_OK
__device__ __forceinline__ void mma_tf32_ss(uint32_t d, uint64_t ad, uint64_t bd,
                                            uint32_t idesc, uint32_t en) {
    asm volatile(
        "{\n\t.reg .pred p;\n\tsetp.ne.u32 p, %5, 0;\n\t"
        "tcgen05.mma.cta_group::1.kind::tf32 [%0], %1, %2, %3, {%4, %4, %4, %4}, p;\n\t}"
        :: "r"(d), "l"(ad), "l"(bd), "r"(idesc), "r"(0u), "r"(en) : "memory");
}

__device__ __forceinline__ void ldtm_x32(uint32_t* r, uint32_t addr) {
    asm volatile(
        "tcgen05.ld.sync.aligned.32x32b.x32.b32 "
        "{%0,%1,%2,%3,%4,%5,%6,%7,%8,%9,%10,%11,%12,%13,%14,%15,"
        "%16,%17,%18,%19,%20,%21,%22,%23,%24,%25,%26,%27,%28,%29,%30,%31}, [%32];"
        : "=r"(r[0]), "=r"(r[1]), "=r"(r[2]), "=r"(r[3]), "=r"(r[4]), "=r"(r[5]), "=r"(r[6]), "=r"(r[7]),
          "=r"(r[8]), "=r"(r[9]), "=r"(r[10]), "=r"(r[11]), "=r"(r[12]), "=r"(r[13]), "=r"(r[14]), "=r"(r[15]),
          "=r"(r[16]), "=r"(r[17]), "=r"(r[18]), "=r"(r[19]), "=r"(r[20]), "=r"(r[21]), "=r"(r[22]), "=r"(r[23]),
          "=r"(r[24]), "=r"(r[25]), "=r"(r[26]), "=r"(r[27]), "=r"(r[28]), "=r"(r[29]), "=r"(r[30]), "=r"(r[31])
        : "r"(addr));
}
#endif

// SW128 K-major blocked-atom layout for a 128x128 fp32 tile.
__device__ __forceinline__ uint32_t tile_off(int row, int k) {
    uint32_t off = ((uint32_t)((k >> 5) * 16 + (row >> 3)) << 10)
                 + ((uint32_t)(row & 7) << 7) + ((uint32_t)(k & 31) << 2);
    return off ^ ((off >> 3) & 0x70);
}

// smem descriptor: SW128, version=1, LBO=1, SBO=64
__device__ __forceinline__ uint64_t make_desc(uint32_t base) {
    const uint64_t BASE = (uint64_t(2) << 61) | (uint64_t(1) << 46)
                        | (uint64_t(64) << 32) | (uint64_t(1) << 16);
    return BASE | ((uint64_t)(base >> 4) & 0x3FFF);
}

constexpr uint32_t IDESC_TF32 = (1u << 4) | (2u << 7) | (2u << 10) | (16u << 17) | (8u << 24);

// Dynamic SMEM layout
constexpr int SMEM_TMEM = 0;
constexpr int SMEM_MB0  = 8;
constexpr int SMEM_MB1  = 16;
constexpr int SMEM_A    = 1024;
constexpr int SMEM_W0   = SMEM_A  + 65536;
constexpr int SMEM_W1   = SMEM_W0 + 65536;
constexpr int SMEM_TOTAL9 = SMEM_W1 + 65536 + 128;
constexpr int SMEM_TOTAL0 = SMEM_W0 + 65536 + 128;

// ---------------------------------------------------------------------------
// Projection GEMM: x = (cemb[cid]+kemb[kid]) @ projW^T + b
// ---------------------------------------------------------------------------
__global__ void __launch_bounds__(128, 1)
tgemm_proj(const int* __restrict__ cid, const int* __restrict__ kid,
           const float* __restrict__ cemb, const float* __restrict__ kemb,
           const float* __restrict__ W, const float* __restrict__ bias,
           float* __restrict__ Cout)
{
#if TC_OK
    extern __shared__ char smem[];
    const uint32_t sb = smem_u32(smem);
    const int tid = threadIdx.x;
    const int wid = tid >> 5;
    const int lid = tid & 31;
    const int vbase = blockIdx.x * 128;
    float* C = Cout + (size_t)vbase * Hd;

    if (wid == 0) TC_ALLOC(sb + SMEM_TMEM, 128);
    else          TC_RELINQ();
    __syncthreads();
    uint32_t tmem;
    asm volatile("ld.shared.b32 %0, [%1];" : "=r"(tmem) : "r"(sb + SMEM_TMEM));

    {
        const float4* ar = (const float4*)(cemb + (size_t)cid[vbase + tid] * Hd);
        const float4* kr = (const float4*)(kemb + (size_t)kid[vbase + tid] * Hd);
        const float4* wr = (const float4*)(W + (size_t)tid * Hd);
#pragma unroll
        for (int c4 = 0; c4 < 32; c4++) {
            float4 a = ar[c4];
            const float4 k = kr[c4];
            a.x += k.x; a.y += k.y; a.z += k.z; a.w += k.w;
            *(uint4*)(smem + SMEM_A + tile_off(tid, c4 * 4)) =
                make_uint4(f2tf32(a.x), f2tf32(a.y), f2tf32(a.z), f2tf32(a.w));
            const float4 w = wr[c4];
            *(uint4*)(smem + SMEM_W0 + tile_off(tid, c4 * 4)) =
                make_uint4(f2tf32(w.x), f2tf32(w.y), f2tf32(w.z), f2tf32(w.w));
        }
    }
    asm volatile("fence.proxy.async.shared::cta;" ::: "memory");
    TC_FENCE_BEFORE();
    __syncthreads();

    if (wid == 0) {
        if (elect_one()) MBAR_INIT(sb + SMEM_MB0, 1);
        __syncwarp();
        TC_FENCE_AFTER();
        const uint64_t ad = make_desc(sb + SMEM_A);
        const uint64_t bd = make_desc(sb + SMEM_W0);
        if (elect_one()) {
#pragma unroll
            for (int s = 0; s < 16; s++) {
                const uint64_t off = (uint64_t)((s >> 2) * 1024 + (s & 3) * 2);
                mma_tf32_ss(tmem, ad + off, bd + off, IDESC_TF32, s > 0 ? 1u : 0u);
            }
            TC_COMMIT(sb + SMEM_MB0);
        }
    }
    __syncthreads();
    mbar_wait(sb + SMEM_MB0, 0);
    TC_FENCE_AFTER();

    const int row = wid * 32 + lid;
    float* crow = C + (size_t)row * Hd;
#pragma unroll
    for (int ch = 0; ch < 4; ch++) {
        uint32_t d[32];
        ldtm_x32(d, tmem + ch * 32);
        TC_WAIT_LD();
#pragma unroll
        for (int q = 0; q < 8; q++) {
            *(float4*)(crow + ch * 32 + q * 4) = make_float4(
                __uint_as_float(d[q*4+0]) + bias[ch*32 + q*4+0],
                __uint_as_float(d[q*4+1]) + bias[ch*32 + q*4+1],
                __uint_as_float(d[q*4+2]) + bias[ch*32 + q*4+2],
                __uint_as_float(d[q*4+3]) + bias[ch*32 + q*4+3]);
        }
    }
    TC_FENCE_BEFORE();
    __syncthreads();
    if (wid == 0) {
        if (elect_one()) MBAR_INVAL(sb + SMEM_MB0);
        TC_DEALLOC(tmem, 128);
    }
#endif
}

// ---------------------------------------------------------------------------
// 9-slab GEMM: one CTA = one 128-row x-block; A loaded once; 9 weights stream
// through double-buffered smem; D ping-pongs between two TMEM buffers.
// ---------------------------------------------------------------------------
__global__ void __launch_bounds__(128, 1)
tgemm9(const float* __restrict__ Asrc,
       const float* __restrict__ selfW,
       const float* __restrict__ relW,
       float* __restrict__ Yout)
{
#if TC_OK
    extern __shared__ char smem[];
    const uint32_t sb = smem_u32(smem);
    const int tid = threadIdx.x;
    const int wid = tid >> 5;
    const int lid = tid & 31;
    const int vbase = blockIdx.x * 128;

    if (wid == 0) TC_ALLOC(sb + SMEM_TMEM, 256);
    else          TC_RELINQ();
    __syncthreads();
    uint32_t tmem;
    asm volatile("ld.shared.b32 %0, [%1];" : "=r"(tmem) : "r"(sb + SMEM_TMEM));

    if (tid == 0) {
        MBAR_INIT(sb + SMEM_MB0, 1);
        MBAR_INIT(sb + SMEM_MB1, 1);
    }

    {
        const float4* ar = (const float4*)(Asrc + (size_t)(vbase + tid) * Hd);
#pragma unroll
        for (int c4 = 0; c4 < 32; c4++) {
            const float4 a = ar[c4];
            *(uint4*)(smem + SMEM_A + tile_off(tid, c4 * 4)) =
                make_uint4(f2tf32(a.x), f2tf32(a.y), f2tf32(a.z), f2tf32(a.w));
        }
    }
    {
        const float4* wr = (const float4*)(selfW + (size_t)tid * Hd);
#pragma unroll
        for (int c4 = 0; c4 < 32; c4++) {
            const float4 w = wr[c4];
            *(uint4*)(smem + SMEM_W0 + tile_off(tid, c4 * 4)) =
                make_uint4(f2tf32(w.x), f2tf32(w.y), f2tf32(w.z), f2tf32(w.w));
        }
    }
    asm volatile("fence.proxy.async.shared::cta;" ::: "memory");
    TC_FENCE_BEFORE();
    __syncthreads();

    const uint64_t ad = make_desc(sb + SMEM_A);
    const int row = wid * 32 + lid;

    for (int j = 0; j < NSLAB; j++) {
        const int buf = j & 1;
        const uint32_t dtm = tmem + buf * 128;

        if (wid == 0) {
            TC_FENCE_AFTER();
            const uint64_t bd = make_desc(sb + (buf ? SMEM_W1 : SMEM_W0));
            if (elect_one()) {
#pragma unroll
                for (int s = 0; s < 16; s++) {
                    const uint64_t off = (uint64_t)((s >> 2) * 1024 + (s & 3) * 2);
                    mma_tf32_ss(dtm, ad + off, bd + off, IDESC_TF32, s > 0 ? 1u : 0u);
                }
                TC_COMMIT(sb + (buf ? SMEM_MB1 : SMEM_MB0));
            }
        }

        if (j + 1 < NSLAB) {
            const float* Wn = relW + (size_t)j * Hd * Hd;
            const float4* wr = (const float4*)(Wn + (size_t)tid * Hd);
            char* wb = smem + ((j + 1) & 1 ? SMEM_W1 : SMEM_W0);
#pragma unroll
            for (int c4 = 0; c4 < 32; c4++) {
                const float4 w = wr[c4];
                *(uint4*)(wb + tile_off(tid, c4 * 4)) =
                    make_uint4(f2tf32(w.x), f2tf32(w.y), f2tf32(w.z), f2tf32(w.w));
            }
        }

        mbar_wait(sb + (buf ? SMEM_MB1 : SMEM_MB0), (j >> 1) & 1);
        TC_FENCE_AFTER();

        float* crow = Yout + ((size_t)j * NV + (size_t)(vbase + row)) * Hd;
#pragma unroll
        for (int ch = 0; ch < 4; ch++) {
            uint32_t d[32];
            ldtm_x32(d, dtm + ch * 32);
            TC_WAIT_LD();
#pragma unroll
            for (int q = 0; q < 8; q++) {
                *(float4*)(crow + ch * 32 + q * 4) = make_float4(
                    __uint_as_float(d[q*4+0]), __uint_as_float(d[q*4+1]),
                    __uint_as_float(d[q*4+2]), __uint_as_float(d[q*4+3]));
            }
        }
        TC_FENCE_BEFORE();
        asm volatile("fence.proxy.async.shared::cta;" ::: "memory");
        __syncthreads();
    }

    if (tid == 0) { MBAR_INVAL(sb + SMEM_MB0); MBAR_INVAL(sb + SMEM_MB1); }
    __syncthreads();
    if (wid == 0) TC_DEALLOC(tmem, 256);
#endif
}

// ---------------------------------------------------------------------------
// Fallback SIMT fp32 GEMM — used only if tcgen05 unavailable.
// ---------------------------------------------------------------------------
template <int MODE>
__launch_bounds__(256)
__global__ void gemm_fb(const float* __restrict__ Asrc,
                        const int*   __restrict__ cid,
                        const int*   __restrict__ kid,
                        const float* __restrict__ cemb,
                        const float* __restrict__ kemb,
                        const float* __restrict__ selfW,
                        const float* __restrict__ relW,
                        const float* __restrict__ bias,
                        float* __restrict__ Cout)
{
    __shared__ float As[32][132];
    __shared__ float Ws[32][132];
    __shared__ int   s_cid[128];
    __shared__ int   s_kid[128];

    const int tid = threadIdx.x;
    const int tx = tid & 15;
    const int ty = tid >> 4;
    const int vbase = blockIdx.x * 128;

    const float* W;
    float* C;
    if (MODE == 0) {
        W = relW;
        C = Cout + (size_t)vbase * Hd;
    } else {
        const int j = blockIdx.y;
        W = (j == 0) ? selfW : (relW + (size_t)(j - 1) * Hd * Hd);
        C = Cout + ((size_t)j * NV + (size_t)vbase) * Hd;
    }

    if (MODE == 0) {
        if (tid < 128) {
            s_cid[tid] = cid[vbase + tid];
            s_kid[tid] = kid[vbase + tid];
        }
        __syncthreads();
    }

    float acc[8][8];
#pragma unroll
    for (int i = 0; i < 8; i++)
#pragma unroll
        for (int j = 0; j < 8; j++) acc[i][j] = 0.0f;

#pragma unroll
    for (int kc = 0; kc < Hd; kc += 32) {
#pragma unroll
        for (int rep = 0; rep < 4; rep++) {
            const int i   = tid + rep * 256;
            const int r   = i >> 3;
            const int c4  = i & 7;
            float4 a;
            if (MODE == 0) {
                const float4 av = ((const float4*)(cemb + (size_t)s_cid[r] * Hd + kc))[c4];
                const float4 kv = ((const float4*)(kemb + (size_t)s_kid[r] * Hd + kc))[c4];
                a = make_float4(av.x + kv.x, av.y + kv.y, av.z + kv.z, av.w + kv.w);
            } else {
                a = *(const float4*)(Asrc + (size_t)(vbase + r) * Hd + kc + c4 * 4);
            }
            As[c4 * 4 + 0][r] = a.x; As[c4 * 4 + 1][r] = a.y;
            As[c4 * 4 + 2][r] = a.z; As[c4 * 4 + 3][r] = a.w;
            const float4 w = *(const float4*)(W + (size_t)r * Hd + kc + c4 * 4);
            Ws[c4 * 4 + 0][r] = w.x; Ws[c4 * 4 + 1][r] = w.y;
            Ws[c4 * 4 + 2][r] = w.z; Ws[c4 * 4 + 3][r] = w.w;
        }
        __syncthreads();

#pragma unroll
        for (int k = 0; k < 32; k++) {
            const float4 a0 = *(const float4*)&As[k][ty * 8];
            const float4 a1 = *(const float4*)&As[k][ty * 8 + 4];
            const float4 w0 = *(const float4*)&Ws[k][tx * 8];
            const float4 w1 = *(const float4*)&Ws[k][tx * 8 + 4];
            const float a[8] = {a0.x, a0.y, a0.z, a0.w, a1.x, a1.y, a1.z, a1.w};
            const float w[8] = {w0.x, w0.y, w0.z, w0.w, w1.x, w1.y, w1.z, w1.w};
#pragma unroll
            for (int i = 0; i < 8; i++)
#pragma unroll
                for (int j = 0; j < 8; j++) acc[i][j] += a[i] * w[j];
        }
        __syncthreads();
    }

    float b0[8];
    if (MODE == 0) {
#pragma unroll
        for (int j = 0; j < 8; j++) b0[j] = bias[tx * 8 + j];
    }
#pragma unroll
    for (int i = 0; i < 8; i++) {
        const int r = ty * 8 + i;
        float4 v0, v1;
        if (MODE == 0) {
            v0 = make_float4(acc[i][0] + b0[0], acc[i][1] + b0[1],
                             acc[i][2] + b0[2], acc[i][3] + b0[3]);
            v1 = make_float4(acc[i][4] + b0[4], acc[i][5] + b0[5],
                             acc[i][6] + b0[6], acc[i][7] + b0[7]);
        } else {
            v0 = make_float4(acc[i][0], acc[i][1], acc[i][2], acc[i][3]);
            v1 = make_float4(acc[i][4], acc[i][5], acc[i][6], acc[i][7]);
        }
        *(float4*)(C + (size_t)r * Hd + tx * 8)     = v0;
        *(float4*)(C + (size_t)r * Hd + tx * 8 + 4) = v1;
    }
}

// ---------------------------------------------------------------------------
// CSR build: histogram -> fast scan (1 CTA, vectorized + shfl) -> placement
// ---------------------------------------------------------------------------
__launch_bounds__(256)
__global__ void zero_int_kernel(int* __restrict__ p, int n)
{
    const int i = blockIdx.x * 256 + threadIdx.x;
    if (i < n) p[i] = 0;
}

__launch_bounds__(256)
__global__ void hist_kernel(const int* __restrict__ dst, int* __restrict__ hist)
{
    const int e = blockIdx.x * 256 + threadIdx.x;
    atomicAdd(&hist[dst[e]], 1);
}

// Scan of 32768 counts: each of 1024 threads owns 32 values (8 independent
// int4 loads), local prefix in registers, shfl warp scan + cross-warp scan.
// Writes both rowstart and cursor (no separate memcpy).
__launch_bounds__(1024)
__global__ void scan_kernel(const int* __restrict__ hist,
                            int* __restrict__ rowstart,
                            int* __restrict__ cursor)
{
    __shared__ int wsums[32];
    const int t = threadIdx.x;
    const int lane = t & 31;
    const int w = t >> 5;

    int4 v[8];
#pragma unroll
    for (int i = 0; i < 8; i++) v[i] = ((const int4*)hist)[t * 8 + i];

    int vals[32];
#pragma unroll
    for (int i = 0; i < 8; i++) {
        vals[4*i+0] = v[i].x; vals[4*i+1] = v[i].y;
        vals[4*i+2] = v[i].z; vals[4*i+3] = v[i].w;
    }
    int local[32];
    int sum = 0;
#pragma unroll
    for (int i = 0; i < 32; i++) { local[i] = sum; sum += vals[i]; }

    // warp-inclusive scan of per-thread sums
    int inc = sum;
#pragma unroll
    for (int d = 1; d < 32; d <<= 1) {
        const int n = __shfl_up_sync(0xFFFFFFFFu, inc, d);
        if (lane >= d) inc += n;
    }
    if (lane == 31) wsums[w] = inc;
    __syncthreads();
    if (w == 0) {
        int x = wsums[lane];
#pragma unroll
        for (int d = 1; d < 32; d <<= 1) {
            const int n = __shfl_up_sync(0xFFFFFFFFu, x, d);
            if (lane >= d) x += n;
        }
        wsums[lane] = x;
    }
    __syncthreads();

    const int excl = inc - sum + (w > 0 ? wsums[w - 1] : 0);
#pragma unroll
    for (int i = 0; i < 8; i++) {
        const int4 o = make_int4(excl + local[4*i+0], excl + local[4*i+1],
                                 excl + local[4*i+2], excl + local[4*i+3]);
        ((int4*)rowstart)[t * 8 + i] = o;
        ((int4*)cursor)[t * 8 + i]   = o;
    }
    if (t == 1023) rowstart[NV] = excl + sum;
}

__launch_bounds__(256)
__global__ void place_kernel(const int* __restrict__ src,
                             const int* __restrict__ dst,
                             const int* __restrict__ et,
                             int* __restrict__ cursor,
                             int* __restrict__ sorted)
{
    const int e = blockIdx.x * 256 + threadIdx.x;
    const int d = dst[e];
    const int pos = atomicAdd(&cursor[d], 1);
    sorted[pos] = ((et[e] + 1) << 15) | src[e];
}

// ---------------------------------------------------------------------------
// Fused gather + update: one warp per dst node.
// out[v] = relu(Y[0][v] + self_b + (sum_{in} Y[slab][src]) / max(deg,1)) [* mask]
// ---------------------------------------------------------------------------
__launch_bounds__(256)
__global__ void gather_update_kernel(const int* __restrict__ rowstart,
                                     const int* __restrict__ sorted,
                                     const float* __restrict__ y,
                                     const float* __restrict__ selfb,
                                     const int*  __restrict__ mask,
                                     float* __restrict__ out,
                                     int apply_mask)
{
    const int v    = blockIdx.x * 8 + (threadIdx.x >> 5);
    const int lane = threadIdx.x & 31;
    const int s = rowstart[v];
    const int e = rowstart[v + 1];

    float4 acc = make_float4(0.f, 0.f, 0.f, 0.f);
    int i = s;
    for (; i + 3 < e; i += 4) {
        const int p0 = sorted[i], p1 = sorted[i + 1], p2 = sorted[i + 2], p3 = sorted[i + 3];
        const float4 a0 = ((const float4*)(y + (size_t)p0 * Hd))[lane];
        const float4 a1 = ((const float4*)(y + (size_t)p1 * Hd))[lane];
        const float4 a2 = ((const float4*)(y + (size_t)p2 * Hd))[lane];
        const float4 a3 = ((const float4*)(y + (size_t)p3 * Hd))[lane];
        acc.x += a0.x + a1.x + a2.x + a3.x;
        acc.y += a0.y + a1.y + a2.y + a3.y;
        acc.z += a0.z + a1.z + a2.z + a3.z;
        acc.w += a0.w + a1.w + a2.w + a3.w;
    }
    for (; i < e; i++) {
        const int p = sorted[i];
        const float4 a = ((const float4*)(y + (size_t)p * Hd))[lane];
        acc.x += a.x; acc.y += a.y; acc.z += a.z; acc.w += a.w;
    }

    const float id = 1.0f / fmaxf((float)(e - s), 1.0f);
    const float4 yv = ((const float4*)(y + (size_t)v * Hd))[lane];
    const float4 b  = ((const float4*)selfb)[lane];
    float m = 1.0f;
    if (apply_mask) m = (float)mask[v];

    float4 r;
    r.x = fmaxf(yv.x + b.x + acc.x * id, 0.0f) * m;
    r.y = fmaxf(yv.y + b.y + acc.y * id, 0.0f) * m;
    r.z = fmaxf(yv.z + b.z + acc.z * id, 0.0f) * m;
    r.w = fmaxf(yv.w + b.w + acc.w * id, 0.0f) * m;
    ((float4*)(out + (size_t)v * Hd))[lane] = r;
}

extern "C" void kernel_launch(void* const* d_in, const int* in_sizes, int n_in,
                              void* d_out, int out_size)
{
    const int*   cid   = (const int*)  d_in[0];
    const int*   kid   = (const int*)  d_in[1];
    const int*   mask  = (const int*)  d_in[2];
    const int*   eidx  = (const int*)  d_in[3];
    const int*   et    = (const int*)  d_in[4];
    const float* cemb  = (const float*)d_in[5];
    const float* kemb  = (const float*)d_in[6];
    const float* projW = (const float*)d_in[7];
    const float* projb = (const float*)d_in[8];
    const float* selfW = (const float*)d_in[9];
    const float* selfb = (const float*)d_in[10];
    const float* relW  = (const float*)d_in[11];

    const int* src = eidx;
    const int* dst = eidx + NE;

    float *x, *x2, *y;
    int *hist, *rowstart, *cursor, *sorted;
    cudaGetSymbolAddress((void**)&x,        g_x);
    cudaGetSymbolAddress((void**)&x2,       g_x2);
    cudaGetSymbolAddress((void**)&y,        g_y);
    cudaGetSymbolAddress((void**)&hist,     g_hist);
    cudaGetSymbolAddress((void**)&rowstart, g_rowstart);
    cudaGetSymbolAddress((void**)&cursor,   g_cursor);
    cudaGetSymbolAddress((void**)&sorted,   g_sorted);

    const int use_tc = g_has_tc;
    if (use_tc) {
        cudaFuncSetAttribute(tgemm_proj, cudaFuncAttributeMaxDynamicSharedMemorySize, SMEM_TOTAL0);
        cudaFuncSetAttribute(tgemm9,     cudaFuncAttributeMaxDynamicSharedMemorySize, SMEM_TOTAL9);
    }

    // --- fork: CSR build on side stream, concurrent with projection GEMM ---
    cudaEventRecord(s_ev_fork, 0);
    cudaStreamWaitEvent(s_side, s_ev_fork, 0);
    zero_int_kernel<<<(NV + 256) / 256, 256, 0, s_side>>>(hist, NV + 1);
    hist_kernel<<<NE / 256, 256, 0, s_side>>>(dst, hist);
    scan_kernel<<<1, 1024, 0, s_side>>>(hist, rowstart, cursor);
    place_kernel<<<NE / 256, 256, 0, s_side>>>(src, dst, et, cursor, sorted);
    cudaEventRecord(s_ev_join, s_side);

    // --- input embedding + projection -> x (main stream, overlapped) ---
    if (use_tc)
        tgemm_proj<<<NV / 128, 128, SMEM_TOTAL0>>>(cid, kid, cemb, kemb, projW, projb, x);
    else
        gemm_fb<0><<<dim3(NV / 128, 1), 256>>>(nullptr, cid, kid, cemb, kemb,
                                               nullptr, projW, projb, x);

    float* cur = x;
    float* nxt = x2;
    for (int l = 0; l < NL; l++) {
        // Y[0] = x @ self_W[l]^T ; Y[1+r] = x @ rel_W[l,r]^T   (needs only x)
        if (use_tc)
            tgemm9<<<NV / 128, 128, SMEM_TOTAL9>>>(
                cur, selfW + (size_t)l * Hd * Hd, relW + (size_t)l * NR * Hd * Hd, y);
        else
            gemm_fb<1><<<dim3(NV / 128, NR + 1), 256>>>(
                cur, nullptr, nullptr, nullptr, nullptr,
                selfW + (size_t)l * Hd * Hd, relW + (size_t)l * NR * Hd * Hd,
                nullptr, y);

        if (l == 0) cudaStreamWaitEvent(0, s_ev_join, 0);   // join CSR before first gather

        float* outp = (l == NL - 1) ? (float*)d_out : nxt;
        gather_update_kernel<<<NV / 8, 256>>>(rowstart, sorted, y, selfb + (size_t)l * Hd,
                                              mask, outp, (l == NL - 1) ? 1 : 0);
        float* tmp = cur; cur = nxt; nxt = tmp;
    }
}

// round 12
// speedup vs baseline: 4.7481x; 1.2375x over previous
#include <cuda_runtime.h>
#include <cuda_bf16.h>
#include <cuda_fp16.h>
#include <cstdint>

// ---------------------------------------------------------------------------
// Arch feature gate: tcgen05 exists only on sm_103a / family 103f.
// ---------------------------------------------------------------------------
#if defined(__CUDA_ARCH__) && (defined(__CUDA_ARCH_FEAT_SM103_ALL) || \
    (defined(__CUDA_ARCH_FAMILY_SPECIFIC__) && (__CUDA_ARCH_FAMILY_SPECIFIC__ == 1030)))
#define TC_OK 1
#else
#define TC_OK 0
#endif

// Problem constants (fixed by dataset)
constexpr int NV = 32768;          // B*N nodes
constexpr int Hd = 128;            // hidden
constexpr int NE = 524288;         // edges
constexpr int NR = 8;              // relations
constexpr int NL = 2;              // layers
constexpr int NSLAB = NR + 1;      // 9: slab 0 = self (fp32), 1..8 = relations (fp16)

// Scratch (static device globals; no allocation at runtime)
__device__ float  g_x [(size_t)NV * Hd];
__device__ float  g_x2[(size_t)NV * Hd];
__device__ float  g_y0[(size_t)NV * Hd];              // self-term slab, fp32
__device__ __half g_yh[(size_t)NR * NV * Hd];         // relation message slabs, fp16
__device__ __align__(16) int g_hist    [NV + 4];
__device__ __align__(16) int g_rowstart[NV + 4];
__device__ __align__(16) int g_cursor  [NV + 4];
__device__ int    g_sorted [NE];                      // (type<<15) | src, grouped by dst
__device__ int    g_tc_flag;

// ---------------------------------------------------------------------------
// Static-init setup: capability probe + side stream/events (pre-capture)
// ---------------------------------------------------------------------------
__global__ void probe_kernel() { g_tc_flag = TC_OK; }

static cudaStream_t s_side;
static cudaEvent_t  s_ev_fork, s_ev_join;

static int setup_once() {
    int v = 0;
    probe_kernel<<<1, 1>>>();
    cudaMemcpyFromSymbol(&v, g_tc_flag, sizeof(int));
    cudaStreamCreateWithFlags(&s_side, cudaStreamNonBlocking);
    cudaEventCreateWithFlags(&s_ev_fork, cudaEventDisableTiming);
    cudaEventCreateWithFlags(&s_ev_join, cudaEventDisableTiming);
    return v;
}
static const int g_has_tc = setup_once();

// ---------------------------------------------------------------------------
// PTX helpers
// ---------------------------------------------------------------------------
__device__ __forceinline__ uint32_t smem_u32(const void* p) {
    uint32_t a;
    asm("{ .reg .u64 t; cvta.to.shared.u64 t, %1; cvt.u32.u64 %0, t; }" : "=r"(a) : "l"(p));
    return a;
}
__device__ __forceinline__ uint32_t elect_one() {
    uint32_t p;
    asm volatile("{\n\t.reg .pred p;\n\telect.sync _|p, 0xFFFFFFFF;\n\tselp.b32 %0, 1, 0, p;\n\t}" : "=r"(p));
    return p;
}
__device__ __forceinline__ uint32_t f2tf32(float f) {
    uint32_t u;
    asm("cvt.rna.tf32.f32 %0, %1;" : "=r"(u) : "f"(f));
    return u;
}

#if TC_OK
#define TC_ALLOC(sm, n)   asm volatile("tcgen05.alloc.cta_group::1.sync.aligned.shared::cta.b32 [%0], %1;" :: "r"(sm), "r"(n) : "memory")
#define TC_DEALLOC(t, n)  asm volatile("tcgen05.dealloc.cta_group::1.sync.aligned.b32 %0, %1;" :: "r"(t), "r"(n))
#define TC_RELINQ()       asm volatile("tcgen05.relinquish_alloc_permit.cta_group::1.sync.aligned;")
#define TC_COMMIT(mb)     asm volatile("tcgen05.commit.cta_group::1.mbarrier::arrive::one.shared::cluster.b64 [%0];" :: "r"(mb) : "memory")
#define TC_WAIT_LD()      asm volatile("tcgen05.wait::ld.sync.aligned;" ::: "memory")
#define TC_FENCE_AFTER()  asm volatile("tcgen05.fence::after_thread_sync;" ::: "memory")
#define TC_FENCE_BEFORE() asm volatile("tcgen05.fence::before_thread_sync;" ::: "memory")
#endif

#define MBAR_INIT(mb, c)  asm volatile("mbarrier.init.shared.b64 [%0], %1;" :: "r"(mb), "r"(c) : "memory")
#define MBAR_INVAL(mb)    asm volatile("mbarrier.inval.shared.b64 [%0];" :: "r"(mb) : "memory")

__device__ __forceinline__ void mbar_wait(uint32_t mb, uint32_t parity) {
    asm volatile(
        "{\n\t.reg .pred P1;\n\t"
        "WL_%=:\n\t"
        "mbarrier.try_wait.parity.acquire.cta.shared::cta.b64 P1, [%0], %1, 0x989680;\n\t"
        "@P1 bra.uni WD_%=;\n\t"
        "bra.uni WL_%=;\n\t"
        "WD_%=:\n\t}"
        :: "r"(mb), "r"(parity) : "memory");
}

#if TC_OK
__device__ __forceinline__ void mma_tf32_ss(uint32_t d, uint64_t ad, uint64_t bd,
                                            uint32_t idesc, uint32_t en) {
    asm volatile(
        "{\n\t.reg .pred p;\n\tsetp.ne.u32 p, %5, 0;\n\t"
        "tcgen05.mma.cta_group::1.kind::tf32 [%0], %1, %2, %3, {%4, %4, %4, %4}, p;\n\t}"
        :: "r"(d), "l"(ad), "l"(bd), "r"(idesc), "r"(0u), "r"(en) : "memory");
}

__device__ __forceinline__ void ldtm_x32(uint32_t* r, uint32_t addr) {
    asm volatile(
        "tcgen05.ld.sync.aligned.32x32b.x32.b32 "
        "{%0,%1,%2,%3,%4,%5,%6,%7,%8,%9,%10,%11,%12,%13,%14,%15,"
        "%16,%17,%18,%19,%20,%21,%22,%23,%24,%25,%26,%27,%28,%29,%30,%31}, [%32];"
        : "=r"(r[0]), "=r"(r[1]), "=r"(r[2]), "=r"(r[3]), "=r"(r[4]), "=r"(r[5]), "=r"(r[6]), "=r"(r[7]),
          "=r"(r[8]), "=r"(r[9]), "=r"(r[10]), "=r"(r[11]), "=r"(r[12]), "=r"(r[13]), "=r"(r[14]), "=r"(r[15]),
          "=r"(r[16]), "=r"(r[17]), "=r"(r[18]), "=r"(r[19]), "=r"(r[20]), "=r"(r[21]), "=r"(r[22]), "=r"(r[23]),
          "=r"(r[24]), "=r"(r[25]), "=r"(r[26]), "=r"(r[27]), "=r"(r[28]), "=r"(r[29]), "=r"(r[30]), "=r"(r[31])
        : "r"(addr));
}
#endif

// SW128 K-major blocked-atom layout for a 128x128 fp32 tile.
__device__ __forceinline__ uint32_t tile_off(int row, int k) {
    uint32_t off = ((uint32_t)((k >> 5) * 16 + (row >> 3)) << 10)
                 + ((uint32_t)(row & 7) << 7) + ((uint32_t)(k & 31) << 2);
    return off ^ ((off >> 3) & 0x70);
}

// smem descriptor: SW128, version=1, LBO=1, SBO=64
__device__ __forceinline__ uint64_t make_desc(uint32_t base) {
    const uint64_t BASE = (uint64_t(2) << 61) | (uint64_t(1) << 46)
                        | (uint64_t(64) << 32) | (uint64_t(1) << 16);
    return BASE | ((uint64_t)(base >> 4) & 0x3FFF);
}

constexpr uint32_t IDESC_TF32 = (1u << 4) | (2u << 7) | (2u << 10) | (16u << 17) | (8u << 24);

// Dynamic SMEM layout
constexpr int SMEM_TMEM = 0;
constexpr int SMEM_MB0  = 8;
constexpr int SMEM_MB1  = 16;
constexpr int SMEM_A    = 1024;
constexpr int SMEM_W0   = SMEM_A  + 65536;
constexpr int SMEM_W1   = SMEM_W0 + 65536;
constexpr int SMEM_TOTAL9 = SMEM_W1 + 65536 + 128;
constexpr int SMEM_TOTAL0 = SMEM_W0 + 65536 + 128;

// ---------------------------------------------------------------------------
// Projection GEMM: x = (cemb[cid]+kemb[kid]) @ projW^T + b
// ---------------------------------------------------------------------------
__global__ void __launch_bounds__(128, 1)
tgemm_proj(const int* __restrict__ cid, const int* __restrict__ kid,
           const float* __restrict__ cemb, const float* __restrict__ kemb,
           const float* __restrict__ W, const float* __restrict__ bias,
           float* __restrict__ Cout)
{
#if TC_OK
    extern __shared__ char smem[];
    const uint32_t sb = smem_u32(smem);
    const int tid = threadIdx.x;
    const int wid = tid >> 5;
    const int lid = tid & 31;
    const int vbase = blockIdx.x * 128;
    float* C = Cout + (size_t)vbase * Hd;

    if (wid == 0) TC_ALLOC(sb + SMEM_TMEM, 128);
    else          TC_RELINQ();
    __syncthreads();
    uint32_t tmem;
    asm volatile("ld.shared.b32 %0, [%1];" : "=r"(tmem) : "r"(sb + SMEM_TMEM));

    {
        const float4* ar = (const float4*)(cemb + (size_t)cid[vbase + tid] * Hd);
        const float4* kr = (const float4*)(kemb + (size_t)kid[vbase + tid] * Hd);
        const float4* wr = (const float4*)(W + (size_t)tid * Hd);
#pragma unroll
        for (int c4 = 0; c4 < 32; c4++) {
            float4 a = ar[c4];
            const float4 k = kr[c4];
            a.x += k.x; a.y += k.y; a.z += k.z; a.w += k.w;
            *(uint4*)(smem + SMEM_A + tile_off(tid, c4 * 4)) =
                make_uint4(f2tf32(a.x), f2tf32(a.y), f2tf32(a.z), f2tf32(a.w));
            const float4 w = wr[c4];
            *(uint4*)(smem + SMEM_W0 + tile_off(tid, c4 * 4)) =
                make_uint4(f2tf32(w.x), f2tf32(w.y), f2tf32(w.z), f2tf32(w.w));
        }
    }
    asm volatile("fence.proxy.async.shared::cta;" ::: "memory");
    TC_FENCE_BEFORE();
    __syncthreads();

    if (wid == 0) {
        if (elect_one()) MBAR_INIT(sb + SMEM_MB0, 1);
        __syncwarp();
        TC_FENCE_AFTER();
        const uint64_t ad = make_desc(sb + SMEM_A);
        const uint64_t bd = make_desc(sb + SMEM_W0);
        if (elect_one()) {
#pragma unroll
            for (int s = 0; s < 16; s++) {
                const uint64_t off = (uint64_t)((s >> 2) * 1024 + (s & 3) * 2);
                mma_tf32_ss(tmem, ad + off, bd + off, IDESC_TF32, s > 0 ? 1u : 0u);
            }
            TC_COMMIT(sb + SMEM_MB0);
        }
    }
    __syncthreads();
    mbar_wait(sb + SMEM_MB0, 0);
    TC_FENCE_AFTER();

    const int row = wid * 32 + lid;
    float* crow = C + (size_t)row * Hd;
#pragma unroll
    for (int ch = 0; ch < 4; ch++) {
        uint32_t d[32];
        ldtm_x32(d, tmem + ch * 32);
        TC_WAIT_LD();
#pragma unroll
        for (int q = 0; q < 8; q++) {
            *(float4*)(crow + ch * 32 + q * 4) = make_float4(
                __uint_as_float(d[q*4+0]) + bias[ch*32 + q*4+0],
                __uint_as_float(d[q*4+1]) + bias[ch*32 + q*4+1],
                __uint_as_float(d[q*4+2]) + bias[ch*32 + q*4+2],
                __uint_as_float(d[q*4+3]) + bias[ch*32 + q*4+3]);
        }
    }
    TC_FENCE_BEFORE();
    __syncthreads();
    if (wid == 0) {
        if (elect_one()) MBAR_INVAL(sb + SMEM_MB0);
        TC_DEALLOC(tmem, 128);
    }
#endif
}

// ---------------------------------------------------------------------------
// 9-slab GEMM: one CTA = one 128-row x-block; A loaded once; 9 weights stream
// through double-buffered smem; D ping-pongs between two TMEM buffers.
// Slab 0 -> y0 (fp32); slabs 1..8 -> yh (fp16).
// ---------------------------------------------------------------------------
__global__ void __launch_bounds__(128, 1)
tgemm9(const float* __restrict__ Asrc,
       const float* __restrict__ selfW,
       const float* __restrict__ relW,
       float* __restrict__ Y0out,
       __half* __restrict__ Yhout)
{
#if TC_OK
    extern __shared__ char smem[];
    const uint32_t sb = smem_u32(smem);
    const int tid = threadIdx.x;
    const int wid = tid >> 5;
    const int lid = tid & 31;
    const int vbase = blockIdx.x * 128;

    if (wid == 0) TC_ALLOC(sb + SMEM_TMEM, 256);
    else          TC_RELINQ();
    __syncthreads();
    uint32_t tmem;
    asm volatile("ld.shared.b32 %0, [%1];" : "=r"(tmem) : "r"(sb + SMEM_TMEM));

    if (tid == 0) {
        MBAR_INIT(sb + SMEM_MB0, 1);
        MBAR_INIT(sb + SMEM_MB1, 1);
    }

    {
        const float4* ar = (const float4*)(Asrc + (size_t)(vbase + tid) * Hd);
#pragma unroll
        for (int c4 = 0; c4 < 32; c4++) {
            const float4 a = ar[c4];
            *(uint4*)(smem + SMEM_A + tile_off(tid, c4 * 4)) =
                make_uint4(f2tf32(a.x), f2tf32(a.y), f2tf32(a.z), f2tf32(a.w));
        }
    }
    {
        const float4* wr = (const float4*)(selfW + (size_t)tid * Hd);
#pragma unroll
        for (int c4 = 0; c4 < 32; c4++) {
            const float4 w = wr[c4];
            *(uint4*)(smem + SMEM_W0 + tile_off(tid, c4 * 4)) =
                make_uint4(f2tf32(w.x), f2tf32(w.y), f2tf32(w.z), f2tf32(w.w));
        }
    }
    asm volatile("fence.proxy.async.shared::cta;" ::: "memory");
    TC_FENCE_BEFORE();
    __syncthreads();

    const uint64_t ad = make_desc(sb + SMEM_A);
    const int row = wid * 32 + lid;

    for (int j = 0; j < NSLAB; j++) {
        const int buf = j & 1;
        const uint32_t dtm = tmem + buf * 128;

        if (wid == 0) {
            TC_FENCE_AFTER();
            const uint64_t bd = make_desc(sb + (buf ? SMEM_W1 : SMEM_W0));
            if (elect_one()) {
#pragma unroll
                for (int s = 0; s < 16; s++) {
                    const uint64_t off = (uint64_t)((s >> 2) * 1024 + (s & 3) * 2);
                    mma_tf32_ss(dtm, ad + off, bd + off, IDESC_TF32, s > 0 ? 1u : 0u);
                }
                TC_COMMIT(sb + (buf ? SMEM_MB1 : SMEM_MB0));
            }
        }

        if (j + 1 < NSLAB) {
            const float* Wn = relW + (size_t)j * Hd * Hd;
            const float4* wr = (const float4*)(Wn + (size_t)tid * Hd);
            char* wb = smem + ((j + 1) & 1 ? SMEM_W1 : SMEM_W0);
#pragma unroll
            for (int c4 = 0; c4 < 32; c4++) {
                const float4 w = wr[c4];
                *(uint4*)(wb + tile_off(tid, c4 * 4)) =
                    make_uint4(f2tf32(w.x), f2tf32(w.y), f2tf32(w.z), f2tf32(w.w));
            }
        }

        mbar_wait(sb + (buf ? SMEM_MB1 : SMEM_MB0), (j >> 1) & 1);
        TC_FENCE_AFTER();

        if (j == 0) {
            float* crow = Y0out + (size_t)(vbase + row) * Hd;
#pragma unroll
            for (int ch = 0; ch < 4; ch++) {
                uint32_t d[32];
                ldtm_x32(d, dtm + ch * 32);
                TC_WAIT_LD();
#pragma unroll
                for (int q = 0; q < 8; q++) {
                    *(float4*)(crow + ch * 32 + q * 4) = make_float4(
                        __uint_as_float(d[q*4+0]), __uint_as_float(d[q*4+1]),
                        __uint_as_float(d[q*4+2]), __uint_as_float(d[q*4+3]));
                }
            }
        } else {
            __half* crow = Yhout + ((size_t)(j - 1) * NV + (size_t)(vbase + row)) * Hd;
#pragma unroll
            for (int ch = 0; ch < 4; ch++) {
                uint32_t d[32];
                ldtm_x32(d, dtm + ch * 32);
                TC_WAIT_LD();
                uint32_t h2[16];
#pragma unroll
                for (int k2 = 0; k2 < 16; k2++) {
                    const __half2 hh = __floats2half2_rn(__uint_as_float(d[2*k2]),
                                                         __uint_as_float(d[2*k2+1]));
                    h2[k2] = *(const uint32_t*)&hh;
                }
                uint4* dstp = (uint4*)(crow + ch * 32);
#pragma unroll
                for (int q = 0; q < 4; q++)
                    dstp[q] = make_uint4(h2[4*q+0], h2[4*q+1], h2[4*q+2], h2[4*q+3]);
            }
        }
        TC_FENCE_BEFORE();
        asm volatile("fence.proxy.async.shared::cta;" ::: "memory");
        __syncthreads();
    }

    if (tid == 0) { MBAR_INVAL(sb + SMEM_MB0); MBAR_INVAL(sb + SMEM_MB1); }
    __syncthreads();
    if (wid == 0) TC_DEALLOC(tmem, 256);
#endif
}

// ---------------------------------------------------------------------------
// Fallback SIMT fp32 GEMM — used only if tcgen05 unavailable.
// MODE0 -> fp32 C. MODE1 -> slab0 fp32 y0, slabs 1..8 fp16 yh.
// ---------------------------------------------------------------------------
template <int MODE>
__launch_bounds__(256)
__global__ void gemm_fb(const float* __restrict__ Asrc,
                        const int*   __restrict__ cid,
                        const int*   __restrict__ kid,
                        const float* __restrict__ cemb,
                        const float* __restrict__ kemb,
                        const float* __restrict__ selfW,
                        const float* __restrict__ relW,
                        const float* __restrict__ bias,
                        float* __restrict__ Cout,
                        __half* __restrict__ Hout)
{
    __shared__ float As[32][132];
    __shared__ float Ws[32][132];
    __shared__ int   s_cid[128];
    __shared__ int   s_kid[128];

    const int tid = threadIdx.x;
    const int tx = tid & 15;
    const int ty = tid >> 4;
    const int vbase = blockIdx.x * 128;

    const float* W;
    float* C = nullptr;
    __half* CH = nullptr;
    int jslab = 0;
    if (MODE == 0) {
        W = relW;
        C = Cout + (size_t)vbase * Hd;
    } else {
        jslab = blockIdx.y;
        W = (jslab == 0) ? selfW : (relW + (size_t)(jslab - 1) * Hd * Hd);
        if (jslab == 0) C = Cout + (size_t)vbase * Hd;
        else            CH = Hout + ((size_t)(jslab - 1) * NV + (size_t)vbase) * Hd;
    }

    if (MODE == 0) {
        if (tid < 128) {
            s_cid[tid] = cid[vbase + tid];
            s_kid[tid] = kid[vbase + tid];
        }
        __syncthreads();
    }

    float acc[8][8];
#pragma unroll
    for (int i = 0; i < 8; i++)
#pragma unroll
        for (int j = 0; j < 8; j++) acc[i][j] = 0.0f;

#pragma unroll
    for (int kc = 0; kc < Hd; kc += 32) {
#pragma unroll
        for (int rep = 0; rep < 4; rep++) {
            const int i   = tid + rep * 256;
            const int r   = i >> 3;
            const int c4  = i & 7;
            float4 a;
            if (MODE == 0) {
                const float4 av = ((const float4*)(cemb + (size_t)s_cid[r] * Hd + kc))[c4];
                const float4 kv = ((const float4*)(kemb + (size_t)s_kid[r] * Hd + kc))[c4];
                a = make_float4(av.x + kv.x, av.y + kv.y, av.z + kv.z, av.w + kv.w);
            } else {
                a = *(const float4*)(Asrc + (size_t)(vbase + r) * Hd + kc + c4 * 4);
            }
            As[c4 * 4 + 0][r] = a.x; As[c4 * 4 + 1][r] = a.y;
            As[c4 * 4 + 2][r] = a.z; As[c4 * 4 + 3][r] = a.w;
            const float4 w = *(const float4*)(W + (size_t)r * Hd + kc + c4 * 4);
            Ws[c4 * 4 + 0][r] = w.x; Ws[c4 * 4 + 1][r] = w.y;
            Ws[c4 * 4 + 2][r] = w.z; Ws[c4 * 4 + 3][r] = w.w;
        }
        __syncthreads();

#pragma unroll
        for (int k = 0; k < 32; k++) {
            const float4 a0 = *(const float4*)&As[k][ty * 8];
            const float4 a1 = *(const float4*)&As[k][ty * 8 + 4];
            const float4 w0 = *(const float4*)&Ws[k][tx * 8];
            const float4 w1 = *(const float4*)&Ws[k][tx * 8 + 4];
            const float a[8] = {a0.x, a0.y, a0.z, a0.w, a1.x, a1.y, a1.z, a1.w};
            const float w[8] = {w0.x, w0.y, w0.z, w0.w, w1.x, w1.y, w1.z, w1.w};
#pragma unroll
            for (int i = 0; i < 8; i++)
#pragma unroll
                for (int j = 0; j < 8; j++) acc[i][j] += a[i] * w[j];
        }
        __syncthreads();
    }

    float b0[8];
    if (MODE == 0) {
#pragma unroll
        for (int j = 0; j < 8; j++) b0[j] = bias[tx * 8 + j];
    }
#pragma unroll
    for (int i = 0; i < 8; i++) {
        const int r = ty * 8 + i;
        if (MODE == 0) {
            *(float4*)(C + (size_t)r * Hd + tx * 8) =
                make_float4(acc[i][0] + b0[0], acc[i][1] + b0[1],
                            acc[i][2] + b0[2], acc[i][3] + b0[3]);
            *(float4*)(C + (size_t)r * Hd + tx * 8 + 4) =
                make_float4(acc[i][4] + b0[4], acc[i][5] + b0[5],
                            acc[i][6] + b0[6], acc[i][7] + b0[7]);
        } else if (jslab == 0) {
            *(float4*)(C + (size_t)r * Hd + tx * 8) =
                make_float4(acc[i][0], acc[i][1], acc[i][2], acc[i][3]);
            *(float4*)(C + (size_t)r * Hd + tx * 8 + 4) =
                make_float4(acc[i][4], acc[i][5], acc[i][6], acc[i][7]);
        } else {
            uint32_t h2[4];
#pragma unroll
            for (int q = 0; q < 4; q++) {
                const __half2 hh = __floats2half2_rn(acc[i][2*q], acc[i][2*q+1]);
                h2[q] = *(const uint32_t*)&hh;
            }
            *(uint4*)(CH + (size_t)r * Hd + tx * 8) = make_uint4(h2[0], h2[1], h2[2], h2[3]);
        }
    }
}

// ---------------------------------------------------------------------------
// CSR build: histogram -> fast scan (1 CTA, vectorized + shfl) -> placement
// ---------------------------------------------------------------------------
__launch_bounds__(256)
__global__ void zero_int_kernel(int* __restrict__ p, int n)
{
    const int i = blockIdx.x * 256 + threadIdx.x;
    if (i < n) p[i] = 0;
}

__launch_bounds__(256)
__global__ void hist_kernel(const int* __restrict__ dst, int* __restrict__ hist)
{
    const int e = blockIdx.x * 256 + threadIdx.x;
    atomicAdd(&hist[dst[e]], 1);
}

__launch_bounds__(1024)
__global__ void scan_kernel(const int* __restrict__ hist,
                            int* __restrict__ rowstart,
                            int* __restrict__ cursor)
{
    __shared__ int wsums[32];
    const int t = threadIdx.x;
    const int lane = t & 31;
    const int w = t >> 5;

    int4 v[8];
#pragma unroll
    for (int i = 0; i < 8; i++) v[i] = ((const int4*)hist)[t * 8 + i];

    int vals[32];
#pragma unroll
    for (int i = 0; i < 8; i++) {
        vals[4*i+0] = v[i].x; vals[4*i+1] = v[i].y;
        vals[4*i+2] = v[i].z; vals[4*i+3] = v[i].w;
    }
    int local[32];
    int sum = 0;
#pragma unroll
    for (int i = 0; i < 32; i++) { local[i] = sum; sum += vals[i]; }

    int inc = sum;
#pragma unroll
    for (int d = 1; d < 32; d <<= 1) {
        const int n = __shfl_up_sync(0xFFFFFFFFu, inc, d);
        if (lane >= d) inc += n;
    }
    if (lane == 31) wsums[w] = inc;
    __syncthreads();
    if (w == 0) {
        int x = wsums[lane];
#pragma unroll
        for (int d = 1; d < 32; d <<= 1) {
            const int n = __shfl_up_sync(0xFFFFFFFFu, x, d);
            if (lane >= d) x += n;
        }
        wsums[lane] = x;
    }
    __syncthreads();

    const int excl = inc - sum + (w > 0 ? wsums[w - 1] : 0);
#pragma unroll
    for (int i = 0; i < 8; i++) {
        const int4 o = make_int4(excl + local[4*i+0], excl + local[4*i+1],
                                 excl + local[4*i+2], excl + local[4*i+3]);
        ((int4*)rowstart)[t * 8 + i] = o;
        ((int4*)cursor)[t * 8 + i]   = o;
    }
    if (t == 1023) rowstart[NV] = excl + sum;
}

__launch_bounds__(256)
__global__ void place_kernel(const int* __restrict__ src,
                             const int* __restrict__ dst,
                             const int* __restrict__ et,
                             int* __restrict__ cursor,
                             int* __restrict__ sorted)
{
    const int e = blockIdx.x * 256 + threadIdx.x;
    const int d = dst[e];
    const int pos = atomicAdd(&cursor[d], 1);
    sorted[pos] = (et[e] << 15) | src[e];    // yh row index = type*NV + src
}

// ---------------------------------------------------------------------------
// Fused gather + update: one warp per dst node.
// out[v] = relu(y0[v] + self_b + (sum_{in} yh[row]) / max(deg,1)) [* mask]
// yh rows are fp16 (256 B); each lane owns 4 consecutive h (uint2 load).
// ---------------------------------------------------------------------------
__launch_bounds__(256)
__global__ void gather_update_kernel(const int* __restrict__ rowstart,
                                     const int* __restrict__ sorted,
                                     const float* __restrict__ y0,
                                     const __half* __restrict__ yh,
                                     const float* __restrict__ selfb,
                                     const int*  __restrict__ mask,
                                     float* __restrict__ out,
                                     int apply_mask)
{
    const int v    = blockIdx.x * 8 + (threadIdx.x >> 5);
    const int lane = threadIdx.x & 31;
    const int s = rowstart[v];
    const int e = rowstart[v + 1];

    float4 acc = make_float4(0.f, 0.f, 0.f, 0.f);
    int i = s;
    for (; i + 3 < e; i += 4) {
        const int p0 = sorted[i], p1 = sorted[i + 1], p2 = sorted[i + 2], p3 = sorted[i + 3];
        const uint2 u0 = ((const uint2*)(yh + (size_t)p0 * Hd))[lane];
        const uint2 u1 = ((const uint2*)(yh + (size_t)p1 * Hd))[lane];
        const uint2 u2 = ((const uint2*)(yh + (size_t)p2 * Hd))[lane];
        const uint2 u3 = ((const uint2*)(yh + (size_t)p3 * Hd))[lane];
#pragma unroll
        for (int q = 0; q < 1; q++) {}   // keep loads batched before converts
        const float2 a0 = __half22float2(*(const __half2*)&u0.x);
        const float2 b0 = __half22float2(*(const __half2*)&u0.y);
        const float2 a1 = __half22float2(*(const __half2*)&u1.x);
        const float2 b1 = __half22float2(*(const __half2*)&u1.y);
        const float2 a2 = __half22float2(*(const __half2*)&u2.x);
        const float2 b2 = __half22float2(*(const __half2*)&u2.y);
        const float2 a3 = __half22float2(*(const __half2*)&u3.x);
        const float2 b3 = __half22float2(*(const __half2*)&u3.y);
        acc.x += (a0.x + a1.x) + (a2.x + a3.x);
        acc.y += (a0.y + a1.y) + (a2.y + a3.y);
        acc.z += (b0.x + b1.x) + (b2.x + b3.x);
        acc.w += (b0.y + b1.y) + (b2.y + b3.y);
    }
    for (; i < e; i++) {
        const int p = sorted[i];
        const uint2 u = ((const uint2*)(yh + (size_t)p * Hd))[lane];
        const float2 a = __half22float2(*(const __half2*)&u.x);
        const float2 b = __half22float2(*(const __half2*)&u.y);
        acc.x += a.x; acc.y += a.y; acc.z += b.x; acc.w += b.y;
    }

    const float id = 1.0f / fmaxf((float)(e - s), 1.0f);
    const float4 yv = ((const float4*)(y0 + (size_t)v * Hd))[lane];
    const float4 b  = ((const float4*)selfb)[lane];
    float m = 1.0f;
    if (apply_mask) m = (float)mask[v];

    float4 r;
    r.x = fmaxf(yv.x + b.x + acc.x * id, 0.0f) * m;
    r.y = fmaxf(yv.y + b.y + acc.y * id, 0.0f) * m;
    r.z = fmaxf(yv.z + b.z + acc.z * id, 0.0f) * m;
    r.w = fmaxf(yv.w + b.w + acc.w * id, 0.0f) * m;
    ((float4*)(out + (size_t)v * Hd))[lane] = r;
}

extern "C" void kernel_launch(void* const* d_in, const int* in_sizes, int n_in,
                              void* d_out, int out_size)
{
    const int*   cid   = (const int*)  d_in[0];
    const int*   kid   = (const int*)  d_in[1];
    const int*   mask  = (const int*)  d_in[2];
    const int*   eidx  = (const int*)  d_in[3];
    const int*   et    = (const int*)  d_in[4];
    const float* cemb  = (const float*)d_in[5];
    const float* kemb  = (const float*)d_in[6];
    const float* projW = (const float*)d_in[7];
    const float* projb = (const float*)d_in[8];
    const float* selfW = (const float*)d_in[9];
    const float* selfb = (const float*)d_in[10];
    const float* relW  = (const float*)d_in[11];

    const int* src = eidx;
    const int* dst = eidx + NE;

    float *x, *x2, *y0;
    __half* yh;
    int *hist, *rowstart, *cursor, *sorted;
    cudaGetSymbolAddress((void**)&x,        g_x);
    cudaGetSymbolAddress((void**)&x2,       g_x2);
    cudaGetSymbolAddress((void**)&y0,       g_y0);
    cudaGetSymbolAddress((void**)&yh,       g_yh);
    cudaGetSymbolAddress((void**)&hist,     g_hist);
    cudaGetSymbolAddress((void**)&rowstart, g_rowstart);
    cudaGetSymbolAddress((void**)&cursor,   g_cursor);
    cudaGetSymbolAddress((void**)&sorted,   g_sorted);

    const int use_tc = g_has_tc;
    if (use_tc) {
        cudaFuncSetAttribute(tgemm_proj, cudaFuncAttributeMaxDynamicSharedMemorySize, SMEM_TOTAL0);
        cudaFuncSetAttribute(tgemm9,     cudaFuncAttributeMaxDynamicSharedMemorySize, SMEM_TOTAL9);
    }

    // --- fork: CSR build on side stream, concurrent with projection GEMM ---
    cudaEventRecord(s_ev_fork, 0);
    cudaStreamWaitEvent(s_side, s_ev_fork, 0);
    zero_int_kernel<<<(NV + 256) / 256, 256, 0, s_side>>>(hist, NV + 1);
    hist_kernel<<<NE / 256, 256, 0, s_side>>>(dst, hist);
    scan_kernel<<<1, 1024, 0, s_side>>>(hist, rowstart, cursor);
    place_kernel<<<NE / 256, 256, 0, s_side>>>(src, dst, et, cursor, sorted);
    cudaEventRecord(s_ev_join, s_side);

    // --- input embedding + projection -> x (main stream, overlapped) ---
    if (use_tc)
        tgemm_proj<<<NV / 128, 128, SMEM_TOTAL0>>>(cid, kid, cemb, kemb, projW, projb, x);
    else
        gemm_fb<0><<<dim3(NV / 128, 1), 256>>>(nullptr, cid, kid, cemb, kemb,
                                               nullptr, projW, projb, x, nullptr);

    float* cur = x;
    float* nxt = x2;
    for (int l = 0; l < NL; l++) {
        if (use_tc)
            tgemm9<<<NV / 128, 128, SMEM_TOTAL9>>>(
                cur, selfW + (size_t)l * Hd * Hd, relW + (size_t)l * NR * Hd * Hd, y0, yh);
        else
            gemm_fb<1><<<dim3(NV / 128, NR + 1), 256>>>(
                cur, nullptr, nullptr, nullptr, nullptr,
                selfW + (size_t)l * Hd * Hd, relW + (size_t)l * NR * Hd * Hd,
                nullptr, y0, yh);

        if (l == 0) cudaStreamWaitEvent(0, s_ev_join, 0);   // join CSR before first gather

        float* outp = (l == NL - 1) ? (float*)d_out : nxt;
        gather_update_kernel<<<NV / 8, 256>>>(rowstart, sorted, y0, yh,
                                              selfb + (size_t)l * Hd, mask, outp,
                                              (l == NL - 1) ? 1 : 0);
        float* tmp = cur; cur = nxt; nxt = tmp;
    }
}